// round 11
// baseline (speedup 1.0000x reference)
#include <cuda_runtime.h>
#include <cuda_bf16.h>
#include <math.h>
#include <stdint.h>

// Problem dims (fixed)
#define BB 4
#define TT 2048
#define CC 1024
#define HH 16
#define DD 64
#define MROWS (BB*TT)          // 8192
#define NFUSE 4096             // Q|K|V|G fused width

// ---------------------------------------------------------------------------
// Device scratch (cudaMalloc banned)
// ---------------------------------------------------------------------------
__device__ float g_QKVG[MROWS*NFUSE];     // fused Q|K|V|G, row stride 4096
__device__ float g_OG[MROWS*CC];          // tf32-rounded gate*o
__device__ float g_Beta[MROWS*HH];
__device__ float g_xt[MROWS*CC];          // tf32-rounded x
__device__ float g_wt[5*CC*CC];           // tf32-rounded Wq|Wk|Wv|Wgate|Wo

// ---------------------------------------------------------------------------
// PTX helpers (base-ISA: mma.sync / ldmatrix / cp.async / cvt.tf32 / f32x2)
// ---------------------------------------------------------------------------
__device__ __forceinline__ uint32_t smem_u32(const void* p) {
    uint32_t a;
    asm("{ .reg .u64 t; cvta.to.shared.u64 t, %1; cvt.u32.u64 %0, t; }" : "=r"(a) : "l"(p));
    return a;
}
__device__ __forceinline__ void cp16(uint32_t dst, const void* src) {
    asm volatile("cp.async.cg.shared.global [%0], [%1], 16;" :: "r"(dst), "l"(src));
}
#define CP_COMMIT() asm volatile("cp.async.commit_group;" ::: "memory")
#define CP_WAIT1()  asm volatile("cp.async.wait_group 1;" ::: "memory")
#define CP_WAIT0()  asm volatile("cp.async.wait_group 0;" ::: "memory")

__device__ __forceinline__ void ldm_x4(uint32_t* r, uint32_t addr) {
    asm volatile("ldmatrix.sync.aligned.m8n8.x4.shared.b16 {%0,%1,%2,%3}, [%4];"
        : "=r"(r[0]), "=r"(r[1]), "=r"(r[2]), "=r"(r[3]) : "r"(addr));
}
__device__ __forceinline__ void mma1688(float* d, uint32_t a0, uint32_t a1,
                                        uint32_t a2, uint32_t a3,
                                        uint32_t b0, uint32_t b1) {
    asm volatile("mma.sync.aligned.m16n8k8.row.col.f32.tf32.tf32.f32 "
        "{%0,%1,%2,%3}, {%4,%5,%6,%7}, {%8,%9}, {%0,%1,%2,%3};"
        : "+f"(d[0]), "+f"(d[1]), "+f"(d[2]), "+f"(d[3])
        : "r"(a0), "r"(a1), "r"(a2), "r"(a3), "r"(b0), "r"(b1));
}
__device__ __forceinline__ float tf32r(float x) {
    float r;
    asm("cvt.rna.tf32.f32 %0, %1;" : "=f"(r) : "f"(x));
    return r;
}
// packed f32x2 ops (Blackwell; PTX-only pattern)
__device__ __forceinline__ void fma2(unsigned long long& d, unsigned long long a,
                                     unsigned long long b) {
    asm("fma.rn.f32x2 %0, %1, %2, %0;" : "+l"(d) : "l"(a), "l"(b));
}
__device__ __forceinline__ unsigned long long add2(unsigned long long a,
                                                   unsigned long long b) {
    unsigned long long d;
    asm("add.rn.f32x2 %0, %1, %2;" : "=l"(d) : "l"(a), "l"(b));
    return d;
}
__device__ __forceinline__ unsigned long long pack2(float lo, float hi) {
    unsigned long long d;
    asm("mov.b64 %0, {%1, %2};" : "=l"(d) : "f"(lo), "f"(hi));
    return d;
}
__device__ __forceinline__ float sum2(unsigned long long v) {
    float lo, hi;
    asm("mov.b64 {%0, %1}, %2;" : "=f"(lo), "=f"(hi) : "l"(v));
    return lo + hi;
}

// ---------------------------------------------------------------------------
// fp32 -> tf32-rounded fp32 (unbiased), float4-vectorized
// ---------------------------------------------------------------------------
__global__ __launch_bounds__(256)
void tf32_round_kernel(const float* __restrict__ in, float* __restrict__ out)
{
    const int i = blockIdx.x * 256 + threadIdx.x;
    float4 v = ((const float4*)in)[i];
    v.x = tf32r(v.x); v.y = tf32r(v.y); v.z = tf32r(v.z); v.w = tf32r(v.w);
    ((float4*)out)[i] = v;
}

__global__ __launch_bounds__(256)
void wround_kernel(const float* __restrict__ w0, const float* __restrict__ w1,
                   const float* __restrict__ w2, const float* __restrict__ w3,
                   const float* __restrict__ w4, float* __restrict__ out)
{
    const int i = blockIdx.x * 256 + threadIdx.x;       // float4 index, 5*WSZ/4
    const int per = (CC * CC) / 4;
    const int which = i / per;
    const int local = i - which * per;
    const float* src = (which == 0) ? w0 : (which == 1) ? w1 :
                       (which == 2) ? w2 : (which == 3) ? w3 : w4;
    float4 v = ((const float4*)src)[local];
    v.x = tf32r(v.x); v.y = tf32r(v.y); v.z = tf32r(v.z); v.w = tf32r(v.w);
    ((float4*)out)[i] = v;
}

// ---------------------------------------------------------------------------
// TF32 HMMA GEMM (unchanged from Round 8/10 — verified passing)
// ---------------------------------------------------------------------------
#define STG_B 32768
#define NSTG  3
#define GEMM_SMEM (NSTG*STG_B)   // 96 KB

__global__ __launch_bounds__(256, 2)
void mma_gemm(const float* __restrict__ Ag, const float* __restrict__ Bg,
              float* __restrict__ Cc, int ldc, int sig_start)
{
    extern __shared__ char smem[];
    const uint32_t sbase = smem_u32(smem);
    const int tid = threadIdx.x;
    const int lane = tid & 31;
    const int wid = tid >> 5;
    const int m_blk = blockIdx.y * 128;
    const int n_blk = blockIdx.x * 128;
    const int warp_m = (wid >> 2) * 64;
    const int warp_n = (wid & 3) * 32;

    const char* pA = (const char*)(Ag + (size_t)m_blk * CC);
    const char* pB = (const char*)(Bg + (size_t)n_blk * CC);

#define LOAD_STAGE(KT, STG) do {                                               \
    const uint32_t sb_ = sbase + (STG) * STG_B;                                \
    const int k0b_ = (KT) * 128;                                               \
    _Pragma("unroll")                                                          \
    for (int j = 0; j < 4; j++) {                                              \
        const int c_ = j * 256 + tid;                                          \
        const int r_ = c_ >> 3, q_ = c_ & 7;                                   \
        const uint32_t so_ = (uint32_t)(r_ * 128 + ((q_ ^ (r_ & 7)) * 16));    \
        const size_t go_ = (size_t)r_ * 4096 + k0b_ + q_ * 16;                 \
        cp16(sb_ + 0     + so_, pA + go_);                                     \
        cp16(sb_ + 16384 + so_, pB + go_);                                     \
    }                                                                          \
    CP_COMMIT();                                                               \
} while (0)

    float acc[4][4][4];
#pragma unroll
    for (int a = 0; a < 4; a++)
#pragma unroll
        for (int b = 0; b < 4; b++)
#pragma unroll
            for (int c = 0; c < 4; c++) acc[a][b][c] = 0.0f;

    const int trow = lane & 7;
    const int tile = lane >> 3;
    const int a_row_add = trow + (tile & 1) * 8;
    const int a_chk_add = tile >> 1;
    const int b_row_add = trow + (tile >> 1) * 8;
    const int b_chk_add = tile & 1;

    LOAD_STAGE(0, 0);
    LOAD_STAGE(1, 1);

    for (int kt = 0; kt < 32; kt++) {
        if (kt + 1 < 32) CP_WAIT1(); else CP_WAIT0();
        __syncthreads();
        const uint32_t st = sbase + (kt % NSTG) * STG_B;

#pragma unroll
        for (int ks = 0; ks < 4; ks++) {
            const int ckbase = 2 * ks;
            uint32_t bfr[2][4];
#pragma unroll
            for (int bi = 0; bi < 2; bi++) {
                const int row = warp_n + bi * 16 + b_row_add;
                const uint32_t q = (uint32_t)((ckbase + b_chk_add) ^ (row & 7));
                ldm_x4(bfr[bi], st + 16384 + (uint32_t)row * 128 + q * 16);
            }
#pragma unroll
            for (int mi = 0; mi < 4; mi++) {
                const int row = warp_m + mi * 16 + a_row_add;
                const uint32_t q = (uint32_t)((ckbase + a_chk_add) ^ (row & 7));
                uint32_t af[4];
                ldm_x4(af, st + (uint32_t)row * 128 + q * 16);
#pragma unroll
                for (int ni = 0; ni < 4; ni++) {
                    uint32_t* bp = &bfr[ni >> 1][(ni & 1) * 2];
                    mma1688(acc[mi][ni], af[0], af[1], af[2], af[3], bp[0], bp[1]);
                }
            }
        }
        __syncthreads();
        if (kt + 2 < 32) LOAD_STAGE(kt + 2, (kt + 2) % NSTG);
    }
#undef LOAD_STAGE

    const int er = lane >> 2;
    const int ec = (lane & 3) * 2;
#pragma unroll
    for (int mi = 0; mi < 4; mi++) {
        const int row = m_blk + warp_m + mi * 16 + er;
#pragma unroll
        for (int ni = 0; ni < 4; ni++) {
            const int col = n_blk + warp_n + ni * 8 + ec;
            float v0 = acc[mi][ni][0], v1 = acc[mi][ni][1];
            float v2 = acc[mi][ni][2], v3 = acc[mi][ni][3];
            if (col >= sig_start) {
                v0 = 1.0f / (1.0f + expf(-v0));
                v1 = 1.0f / (1.0f + expf(-v1));
                v2 = 1.0f / (1.0f + expf(-v2));
                v3 = 1.0f / (1.0f + expf(-v3));
            }
            float2 lo2 = {v0, v1}, hi2 = {v2, v3};
            *(float2*)&Cc[(size_t)row * ldc + col] = lo2;
            *(float2*)&Cc[(size_t)(row + 8) * ldc + col] = hi2;
        }
    }
}

// ---------------------------------------------------------------------------
// beta = sigmoid(x @ Wbeta^T + bbeta) : (8192, 16)
// float4 LDS, dual accumulators (issue-count cut 4x vs scalar version)
// ---------------------------------------------------------------------------
__global__ __launch_bounds__(512)
void beta_kernel(const float* __restrict__ x, const float* __restrict__ Wb,
                 const float* __restrict__ bb, float* __restrict__ Beta)
{
    __shared__ __align__(16) float xs[CC];
    const int row = blockIdx.x;
    const int tid = threadIdx.x;
    if (tid < 256)
        ((float4*)xs)[tid] = ((const float4*)&x[(size_t)row * CC])[tid];
    __syncthreads();

    const int h = tid >> 5;
    const int lane = tid & 31;
    const float4* w4 = (const float4*)&Wb[(size_t)h * CC];
    const float4* x4 = (const float4*)xs;
    float accA = 0.0f, accB = 0.0f;
#pragma unroll
    for (int c = 0; c < 8; c += 2) {
        float4 a0 = x4[lane + (c + 0) * 32], b0 = w4[lane + (c + 0) * 32];
        float4 a1 = x4[lane + (c + 1) * 32], b1 = w4[lane + (c + 1) * 32];
        accA = fmaf(a0.x, b0.x, accA); accA = fmaf(a0.y, b0.y, accA);
        accA = fmaf(a0.z, b0.z, accA); accA = fmaf(a0.w, b0.w, accA);
        accB = fmaf(a1.x, b1.x, accB); accB = fmaf(a1.y, b1.y, accB);
        accB = fmaf(a1.z, b1.z, accB); accB = fmaf(a1.w, b1.w, accB);
    }
    float acc = accA + accB;
#pragma unroll
    for (int off = 16; off > 0; off >>= 1)
        acc += __shfl_xor_sync(0xffffffffu, acc, off);
    if (lane == 0) {
        float v = acc + bb[h];
        Beta[(size_t)row * HH + h] = 1.0f / (1.0f + expf(-v));
    }
}

// ---------------------------------------------------------------------------
// L2-normalize Q and K per (row, head) over D=64 (in fused QKVG buffer)
// ---------------------------------------------------------------------------
__global__ __launch_bounds__(256)
void norm_kernel()
{
    const int gw = blockIdx.x * 8 + (threadIdx.x >> 5);
    const int lane = threadIdx.x & 31;
    const int which = gw & 1;
    const int rem = gw >> 1;
    const int row = rem >> 4;
    const int h = rem & 15;
    float* p = &g_QKVG[(size_t)row * NFUSE + which * CC + h * DD];
    float v0 = p[lane];
    float v1 = p[lane + 32];
    float s = v0 * v0 + v1 * v1;
#pragma unroll
    for (int off = 16; off > 0; off >>= 1)
        s += __shfl_xor_sync(0xffffffffu, s, off);
    float n = sqrtf(s);
    float scale = 1.0f / fmaxf(n, 1e-12f);
    p[lane]      = v0 * scale;
    p[lane + 32] = v1 * scale;
}

// ---------------------------------------------------------------------------
// Delta-rule scan, packed-f32x2 math. One block per (b,h). 256 threads.
// Thread t: row d = t>>2, column group cg = t&3 (16 cols = 8 packed pairs).
// M in 8 packed regs; q/k loaded as ulonglong2 (LDS.128 -> 2 packed regs).
// FMA issues per step per thread: 24 (was 48).
// 4 smem buffers, one barrier per 2 steps, LDG->STS distance 6 steps.
// ---------------------------------------------------------------------------
__global__ __launch_bounds__(256, 1)
void scan_kernel()
{
    const int b = blockIdx.x >> 4;
    const int h = blockIdx.x & 15;
    __shared__ __align__(16) float s[4][256];  // [0:64)q [64:128)k [128:192)v [192:256)g
    __shared__ float sbv[4];

    const int t = threadIdx.x;
    const int d = t >> 2;
    const int cg = t & 3;
    const int cbase = cg * 16;
    const int arr = t >> 6;
    const int idx = t & 63;
    const float* src = g_QKVG + (size_t)arr * CC + (size_t)h * DD + idx;
    const size_t rbase = (size_t)b * TT;

    unsigned long long M2[8];
#pragma unroll
    for (int j = 0; j < 8; j++) M2[j] = 0ull;

    float f0a = src[(rbase + 0) * NFUSE], f0b = src[(rbase + 1) * NFUSE];
    float f1a = src[(rbase + 2) * NFUSE], f1b = src[(rbase + 3) * NFUSE];
    float f2a = src[(rbase + 4) * NFUSE], f2b = src[(rbase + 5) * NFUSE];
    float f3a = src[(rbase + 6) * NFUSE], f3b = src[(rbase + 7) * NFUSE];
    float b0a = 0, b0b = 0, b1a = 0, b1b = 0, b2a = 0, b2b = 0, b3a = 0, b3b = 0;
    if (t == 0) {
        b0a = g_Beta[(rbase + 0) * HH + h]; b0b = g_Beta[(rbase + 1) * HH + h];
        b1a = g_Beta[(rbase + 2) * HH + h]; b1b = g_Beta[(rbase + 3) * HH + h];
        b2a = g_Beta[(rbase + 4) * HH + h]; b2b = g_Beta[(rbase + 5) * HH + h];
        b3a = g_Beta[(rbase + 6) * HH + h]; b3b = g_Beta[(rbase + 7) * HH + h];
    }
    s[0][t] = f0a; s[1][t] = f0b;
    if (t == 0) { sbv[0] = b0a; sbv[1] = b0b; }
    __syncthreads();

#define SCAN_STEP(STEP, RB)                                                           \
    {                                                                                 \
        const ulonglong2* sq2 = (const ulonglong2*)&s[RB][cbase];                     \
        const ulonglong2* sk2 = (const ulonglong2*)&s[RB][64 + cbase];                \
        const float sb = sbv[RB];                                                     \
        unsigned long long poA = 0ull, poB = 0ull, pkA = 0ull, pkB = 0ull;            \
        unsigned long long k2[8];                                                     \
        _Pragma("unroll")                                                             \
        for (int jj = 0; jj < 4; jj++) {                                              \
            ulonglong2 qv = sq2[jj];                                                  \
            ulonglong2 kv = sk2[jj];                                                  \
            k2[2*jj] = kv.x; k2[2*jj+1] = kv.y;                                       \
            fma2(poA, M2[2*jj],   qv.x);                                              \
            fma2(poB, M2[2*jj+1], qv.y);                                              \
            fma2(pkA, M2[2*jj],   kv.x);                                              \
            fma2(pkB, M2[2*jj+1], kv.y);                                              \
        }                                                                             \
        float po = sum2(add2(poA, poB));                                              \
        float pk = sum2(add2(pkA, pkB));                                              \
        po += __shfl_xor_sync(0xffffffffu, po, 1);                                    \
        pk += __shfl_xor_sync(0xffffffffu, pk, 1);                                    \
        po += __shfl_xor_sync(0xffffffffu, po, 2);                                    \
        pk += __shfl_xor_sync(0xffffffffu, pk, 2);                                    \
        const float dv = s[RB][128 + d] - pk;                                         \
        const float bdv = sb * dv;                                                    \
        const unsigned long long bdv2 = pack2(bdv, bdv);                              \
        _Pragma("unroll")                                                             \
        for (int jj = 0; jj < 8; jj++)                                                \
            fma2(M2[jj], bdv2, k2[jj]);                                               \
        if (cg == 0)                                                                  \
            g_OG[(rbase + (STEP)) * CC + h * DD + d] = tf32r(s[RB][192 + d] * po);    \
    }

#define WINDOW(J, RB0, RB1, WB0, WB1, SFA, SFB, SBA, SBB, LFA, LFB, LBA, LBB)         \
    {                                                                                 \
        int ls = 2 * (J) + 8; if (ls > TT - 2) ls = TT - 2;                           \
        LFA = src[(rbase + ls) * NFUSE];                                              \
        LFB = src[(rbase + ls + 1) * NFUSE];                                          \
        if (t == 0) {                                                                 \
            LBA = g_Beta[(rbase + ls) * HH + h];                                      \
            LBB = g_Beta[(rbase + ls + 1) * HH + h];                                  \
        }                                                                             \
        s[WB0][t] = SFA; s[WB1][t] = SFB;                                             \
        if (t == 0) { sbv[WB0] = SBA; sbv[WB1] = SBB; }                               \
        SCAN_STEP(2 * (J),     RB0);                                                  \
        SCAN_STEP(2 * (J) + 1, RB1);                                                  \
        __syncthreads();                                                              \
    }

    for (int m = 0; m < TT / 8; m++) {
        const int j0 = 4 * m;
        WINDOW(j0 + 0, 0, 1, 2, 3, f1a, f1b, b1a, b1b, f0a, f0b, b0a, b0b);
        WINDOW(j0 + 1, 2, 3, 0, 1, f2a, f2b, b2a, b2b, f1a, f1b, b1a, b1b);
        WINDOW(j0 + 2, 0, 1, 2, 3, f3a, f3b, b3a, b3b, f2a, f2b, b2a, b2b);
        WINDOW(j0 + 3, 2, 3, 0, 1, f0a, f0b, b0a, b0b, f3a, f3b, b3a, b3b);
    }
#undef WINDOW
#undef SCAN_STEP
}

// ---------------------------------------------------------------------------
extern "C" void kernel_launch(void* const* d_in, const int* in_sizes, int n_in,
                              void* d_out, int out_size)
{
    const float* x     = (const float*)d_in[0];
    const float* Wq    = (const float*)d_in[1];
    const float* Wk    = (const float*)d_in[2];
    const float* Wv    = (const float*)d_in[3];
    const float* Wbeta = (const float*)d_in[4];
    const float* bbeta = (const float*)d_in[5];
    const float* Wgate = (const float*)d_in[6];
    const float* Wo    = (const float*)d_in[7];
    float* out = (float*)d_out;

    float *QKVGp, *OGp, *Bp, *xtp, *wtp;
    cudaGetSymbolAddress((void**)&QKVGp, g_QKVG);
    cudaGetSymbolAddress((void**)&OGp,   g_OG);
    cudaGetSymbolAddress((void**)&Bp,    g_Beta);
    cudaGetSymbolAddress((void**)&xtp,   g_xt);
    cudaGetSymbolAddress((void**)&wtp,   g_wt);

    cudaFuncSetAttribute(mma_gemm, cudaFuncAttributeMaxDynamicSharedMemorySize, GEMM_SMEM);

    const int WSZ = CC * CC;

    tf32_round_kernel<<<MROWS * CC / 4 / 256, 256>>>(x, xtp);
    wround_kernel<<<5 * WSZ / 4 / 256, 256>>>(Wq, Wk, Wv, Wgate, Wo, wtp);

    dim3 fgrid(NFUSE / 128, MROWS / 128);
    mma_gemm<<<fgrid, 256, GEMM_SMEM>>>(xtp, wtp, QKVGp, NFUSE, 3 * CC);

    beta_kernel<<<MROWS, 512>>>(x, Wbeta, bbeta, Bp);
    norm_kernel<<<(2 * MROWS * HH) / 8, 256>>>();
    scan_kernel<<<BB * HH, 256>>>();

    dim3 ogrid(CC / 128, MROWS / 128);
    mma_gemm<<<ogrid, 256, GEMM_SMEM>>>(OGp, wtp + 4 * WSZ, out, CC, 1 << 30);
}

// round 12
// speedup vs baseline: 1.8574x; 1.8574x over previous
#include <cuda_runtime.h>
#include <cuda_bf16.h>
#include <math.h>
#include <stdint.h>

// Problem dims (fixed)
#define BB 4
#define TT 2048
#define CC 1024
#define HH 16
#define DD 64
#define MROWS (BB*TT)          // 8192
#define NFUSE 4096             // Q|K|V|G fused width

// ---------------------------------------------------------------------------
// Device scratch (cudaMalloc banned)
// ---------------------------------------------------------------------------
__device__ float g_QKVG[MROWS*NFUSE];     // fused Q|K|V|G, row stride 4096
__device__ float g_OG[MROWS*CC];          // tf32-rounded gate*o
__device__ float g_Beta[MROWS*HH];
__device__ float g_xt[MROWS*CC];          // tf32-rounded x
__device__ float g_wt[5*CC*CC];           // tf32-rounded Wq|Wk|Wv|Wgate|Wo

// ---------------------------------------------------------------------------
// PTX helpers (base-ISA only: mma.sync / ldmatrix / cp.async / cvt.tf32)
// ---------------------------------------------------------------------------
__device__ __forceinline__ uint32_t smem_u32(const void* p) {
    uint32_t a;
    asm("{ .reg .u64 t; cvta.to.shared.u64 t, %1; cvt.u32.u64 %0, t; }" : "=r"(a) : "l"(p));
    return a;
}
__device__ __forceinline__ void cp16(uint32_t dst, const void* src) {
    asm volatile("cp.async.cg.shared.global [%0], [%1], 16;" :: "r"(dst), "l"(src));
}
#define CP_COMMIT() asm volatile("cp.async.commit_group;" ::: "memory")
#define CP_WAIT1()  asm volatile("cp.async.wait_group 1;" ::: "memory")
#define CP_WAIT0()  asm volatile("cp.async.wait_group 0;" ::: "memory")

__device__ __forceinline__ void ldm_x4(uint32_t* r, uint32_t addr) {
    asm volatile("ldmatrix.sync.aligned.m8n8.x4.shared.b16 {%0,%1,%2,%3}, [%4];"
        : "=r"(r[0]), "=r"(r[1]), "=r"(r[2]), "=r"(r[3]) : "r"(addr));
}
__device__ __forceinline__ void mma1688(float* d, uint32_t a0, uint32_t a1,
                                        uint32_t a2, uint32_t a3,
                                        uint32_t b0, uint32_t b1) {
    asm volatile("mma.sync.aligned.m16n8k8.row.col.f32.tf32.tf32.f32 "
        "{%0,%1,%2,%3}, {%4,%5,%6,%7}, {%8,%9}, {%0,%1,%2,%3};"
        : "+f"(d[0]), "+f"(d[1]), "+f"(d[2]), "+f"(d[3])
        : "r"(a0), "r"(a1), "r"(a2), "r"(a3), "r"(b0), "r"(b1));
}
__device__ __forceinline__ float tf32r(float x) {
    float r;
    asm("cvt.rna.tf32.f32 %0, %1;" : "=f"(r) : "f"(x));
    return r;
}

// ---------------------------------------------------------------------------
// fp32 -> tf32-rounded fp32 (unbiased), float4-vectorized
// ---------------------------------------------------------------------------
__global__ __launch_bounds__(256)
void tf32_round_kernel(const float* __restrict__ in, float* __restrict__ out)
{
    const int i = blockIdx.x * 256 + threadIdx.x;
    float4 v = ((const float4*)in)[i];
    v.x = tf32r(v.x); v.y = tf32r(v.y); v.z = tf32r(v.z); v.w = tf32r(v.w);
    ((float4*)out)[i] = v;
}

__global__ __launch_bounds__(256)
void wround_kernel(const float* __restrict__ w0, const float* __restrict__ w1,
                   const float* __restrict__ w2, const float* __restrict__ w3,
                   const float* __restrict__ w4, float* __restrict__ out)
{
    const int i = blockIdx.x * 256 + threadIdx.x;       // float4 index, 5*WSZ/4
    const int per = (CC * CC) / 4;
    const int which = i / per;
    const int local = i - which * per;
    const float* src = (which == 0) ? w0 : (which == 1) ? w1 :
                       (which == 2) ? w2 : (which == 3) ? w3 : w4;
    float4 v = ((const float4*)src)[local];
    v.x = tf32r(v.x); v.y = tf32r(v.y); v.z = tf32r(v.z); v.w = tf32r(v.w);
    ((float4*)out)[i] = v;
}

// ---------------------------------------------------------------------------
// TF32 HMMA GEMM (unchanged from Round 8/10 — verified passing)
// ---------------------------------------------------------------------------
#define STG_B 32768
#define NSTG  3
#define GEMM_SMEM (NSTG*STG_B)   // 96 KB

__global__ __launch_bounds__(256, 2)
void mma_gemm(const float* __restrict__ Ag, const float* __restrict__ Bg,
              float* __restrict__ Cc, int ldc, int sig_start)
{
    extern __shared__ char smem[];
    const uint32_t sbase = smem_u32(smem);
    const int tid = threadIdx.x;
    const int lane = tid & 31;
    const int wid = tid >> 5;
    const int m_blk = blockIdx.y * 128;
    const int n_blk = blockIdx.x * 128;
    const int warp_m = (wid >> 2) * 64;
    const int warp_n = (wid & 3) * 32;

    const char* pA = (const char*)(Ag + (size_t)m_blk * CC);
    const char* pB = (const char*)(Bg + (size_t)n_blk * CC);

#define LOAD_STAGE(KT, STG) do {                                               \
    const uint32_t sb_ = sbase + (STG) * STG_B;                                \
    const int k0b_ = (KT) * 128;                                               \
    _Pragma("unroll")                                                          \
    for (int j = 0; j < 4; j++) {                                              \
        const int c_ = j * 256 + tid;                                          \
        const int r_ = c_ >> 3, q_ = c_ & 7;                                   \
        const uint32_t so_ = (uint32_t)(r_ * 128 + ((q_ ^ (r_ & 7)) * 16));    \
        const size_t go_ = (size_t)r_ * 4096 + k0b_ + q_ * 16;                 \
        cp16(sb_ + 0     + so_, pA + go_);                                     \
        cp16(sb_ + 16384 + so_, pB + go_);                                     \
    }                                                                          \
    CP_COMMIT();                                                               \
} while (0)

    float acc[4][4][4];
#pragma unroll
    for (int a = 0; a < 4; a++)
#pragma unroll
        for (int b = 0; b < 4; b++)
#pragma unroll
            for (int c = 0; c < 4; c++) acc[a][b][c] = 0.0f;

    const int trow = lane & 7;
    const int tile = lane >> 3;
    const int a_row_add = trow + (tile & 1) * 8;
    const int a_chk_add = tile >> 1;
    const int b_row_add = trow + (tile >> 1) * 8;
    const int b_chk_add = tile & 1;

    LOAD_STAGE(0, 0);
    LOAD_STAGE(1, 1);

    for (int kt = 0; kt < 32; kt++) {
        if (kt + 1 < 32) CP_WAIT1(); else CP_WAIT0();
        __syncthreads();
        const uint32_t st = sbase + (kt % NSTG) * STG_B;

#pragma unroll
        for (int ks = 0; ks < 4; ks++) {
            const int ckbase = 2 * ks;
            uint32_t bfr[2][4];
#pragma unroll
            for (int bi = 0; bi < 2; bi++) {
                const int row = warp_n + bi * 16 + b_row_add;
                const uint32_t q = (uint32_t)((ckbase + b_chk_add) ^ (row & 7));
                ldm_x4(bfr[bi], st + 16384 + (uint32_t)row * 128 + q * 16);
            }
#pragma unroll
            for (int mi = 0; mi < 4; mi++) {
                const int row = warp_m + mi * 16 + a_row_add;
                const uint32_t q = (uint32_t)((ckbase + a_chk_add) ^ (row & 7));
                uint32_t af[4];
                ldm_x4(af, st + (uint32_t)row * 128 + q * 16);
#pragma unroll
                for (int ni = 0; ni < 4; ni++) {
                    uint32_t* bp = &bfr[ni >> 1][(ni & 1) * 2];
                    mma1688(acc[mi][ni], af[0], af[1], af[2], af[3], bp[0], bp[1]);
                }
            }
        }
        __syncthreads();
        if (kt + 2 < 32) LOAD_STAGE(kt + 2, (kt + 2) % NSTG);
    }
#undef LOAD_STAGE

    const int er = lane >> 2;
    const int ec = (lane & 3) * 2;
#pragma unroll
    for (int mi = 0; mi < 4; mi++) {
        const int row = m_blk + warp_m + mi * 16 + er;
#pragma unroll
        for (int ni = 0; ni < 4; ni++) {
            const int col = n_blk + warp_n + ni * 8 + ec;
            float v0 = acc[mi][ni][0], v1 = acc[mi][ni][1];
            float v2 = acc[mi][ni][2], v3 = acc[mi][ni][3];
            if (col >= sig_start) {
                v0 = 1.0f / (1.0f + expf(-v0));
                v1 = 1.0f / (1.0f + expf(-v1));
                v2 = 1.0f / (1.0f + expf(-v2));
                v3 = 1.0f / (1.0f + expf(-v3));
            }
            float2 lo2 = {v0, v1}, hi2 = {v2, v3};
            *(float2*)&Cc[(size_t)row * ldc + col] = lo2;
            *(float2*)&Cc[(size_t)(row + 8) * ldc + col] = hi2;
        }
    }
}

// ---------------------------------------------------------------------------
// beta = sigmoid(x @ Wbeta^T + bbeta) : (8192, 16)   (R10 version — 47us)
// ---------------------------------------------------------------------------
__global__ __launch_bounds__(512)
void beta_kernel(const float* __restrict__ x, const float* __restrict__ Wb,
                 const float* __restrict__ bb, float* __restrict__ Beta)
{
    __shared__ float xs[CC];
    const int row = blockIdx.x;
    const int tid = threadIdx.x;
    for (int i = tid; i < CC; i += 512) xs[i] = x[(size_t)row * CC + i];
    __syncthreads();

    const int h = tid >> 5;
    const int lane = tid & 31;
    const float* wrow = &Wb[(size_t)h * CC];
    float acc = 0.0f;
#pragma unroll 8
    for (int c = lane; c < CC; c += 32) acc = fmaf(xs[c], wrow[c], acc);
#pragma unroll
    for (int off = 16; off > 0; off >>= 1)
        acc += __shfl_xor_sync(0xffffffffu, acc, off);
    if (lane == 0) {
        float v = acc + bb[h];
        Beta[(size_t)row * HH + h] = 1.0f / (1.0f + expf(-v));
    }
}

// ---------------------------------------------------------------------------
// L2-normalize Q and K per (row, head) over D=64 (in fused QKVG buffer)
// ---------------------------------------------------------------------------
__global__ __launch_bounds__(256)
void norm_kernel()
{
    const int gw = blockIdx.x * 8 + (threadIdx.x >> 5);
    const int lane = threadIdx.x & 31;
    const int which = gw & 1;
    const int rem = gw >> 1;
    const int row = rem >> 4;
    const int h = rem & 15;
    float* p = &g_QKVG[(size_t)row * NFUSE + which * CC + h * DD];
    float v0 = p[lane];
    float v1 = p[lane + 32];
    float s = v0 * v0 + v1 * v1;
#pragma unroll
    for (int off = 16; off > 0; off >>= 1)
        s += __shfl_xor_sync(0xffffffffu, s, off);
    float n = sqrtf(s);
    float scale = 1.0f / fmaxf(n, 1e-12f);
    p[lane]      = v0 * scale;
    p[lane + 32] = v1 * scale;
}

// ---------------------------------------------------------------------------
// Delta-rule scan, ROW-SPLIT: M's rows are independent given the broadcast
// q/k/v/g/beta, so each (b,h) is split across 2 CTAs (rows 0-31 / 32-63).
// 128 CTAs fill 128 SMs -> per-SMSP FMA work per step halves vs R10.
// 256 threads: 8 threads/row (8 cols each), 3-level shfl reduction.
// 4 smem buffers, one barrier per 2 steps, LDG->STS distance 6 steps (R10).
// ---------------------------------------------------------------------------
__global__ __launch_bounds__(256, 1)
void scan_kernel()
{
    const int bh = blockIdx.x >> 1;
    const int half = blockIdx.x & 1;
    const int b = bh >> 4;
    const int h = bh & 15;
    __shared__ __align__(16) float s[4][256];  // [0:64)q [64:128)k [128:192)v [192:256)g
    __shared__ float sbv[4];

    const int t = threadIdx.x;
    const int d = half * 32 + (t >> 3);   // global row 0..63
    const int cg = t & 7;                 // column group (8 cols)
    const int cbase = cg * 8;

    const int arr = t >> 6;               // loader quarter: 0=q 1=k 2=v 3=g
    const int idx = t & 63;
    const float* src = g_QKVG + (size_t)arr * CC + (size_t)h * DD + idx;
    const size_t rbase = (size_t)b * TT;

    float Mreg[8];
#pragma unroll
    for (int j = 0; j < 8; j++) Mreg[j] = 0.0f;

    // register queue slots 0..3 hold pairs 0..3 (steps 0..7)
    float f0a = src[(rbase + 0) * NFUSE], f0b = src[(rbase + 1) * NFUSE];
    float f1a = src[(rbase + 2) * NFUSE], f1b = src[(rbase + 3) * NFUSE];
    float f2a = src[(rbase + 4) * NFUSE], f2b = src[(rbase + 5) * NFUSE];
    float f3a = src[(rbase + 6) * NFUSE], f3b = src[(rbase + 7) * NFUSE];
    float b0a = 0, b0b = 0, b1a = 0, b1b = 0, b2a = 0, b2b = 0, b3a = 0, b3b = 0;
    if (t == 0) {
        b0a = g_Beta[(rbase + 0) * HH + h]; b0b = g_Beta[(rbase + 1) * HH + h];
        b1a = g_Beta[(rbase + 2) * HH + h]; b1b = g_Beta[(rbase + 3) * HH + h];
        b2a = g_Beta[(rbase + 4) * HH + h]; b2b = g_Beta[(rbase + 5) * HH + h];
        b3a = g_Beta[(rbase + 6) * HH + h]; b3b = g_Beta[(rbase + 7) * HH + h];
    }
    s[0][t] = f0a; s[1][t] = f0b;
    if (t == 0) { sbv[0] = b0a; sbv[1] = b0b; }
    __syncthreads();

#define SCAN_STEP(STEP, RB)                                                           \
    {                                                                                 \
        const float4* sq4 = (const float4*)&s[RB][cbase];                             \
        const float4* sk4 = (const float4*)&s[RB][64 + cbase];                        \
        const float sb = sbv[RB];                                                     \
        float4 qv0 = sq4[0], qv1 = sq4[1];                                            \
        float4 kv0 = sk4[0], kv1 = sk4[1];                                            \
        float poA = 0.0f, pkA = 0.0f, poB = 0.0f, pkB = 0.0f;                         \
        poA = fmaf(Mreg[0], qv0.x, poA); pkA = fmaf(Mreg[0], kv0.x, pkA);             \
        poA = fmaf(Mreg[1], qv0.y, poA); pkA = fmaf(Mreg[1], kv0.y, pkA);             \
        poA = fmaf(Mreg[2], qv0.z, poA); pkA = fmaf(Mreg[2], kv0.z, pkA);             \
        poA = fmaf(Mreg[3], qv0.w, poA); pkA = fmaf(Mreg[3], kv0.w, pkA);             \
        poB = fmaf(Mreg[4], qv1.x, poB); pkB = fmaf(Mreg[4], kv1.x, pkB);             \
        poB = fmaf(Mreg[5], qv1.y, poB); pkB = fmaf(Mreg[5], kv1.y, pkB);             \
        poB = fmaf(Mreg[6], qv1.z, poB); pkB = fmaf(Mreg[6], kv1.z, pkB);             \
        poB = fmaf(Mreg[7], qv1.w, poB); pkB = fmaf(Mreg[7], kv1.w, pkB);             \
        float po = poA + poB, pk = pkA + pkB;                                         \
        po += __shfl_xor_sync(0xffffffffu, po, 1);                                    \
        pk += __shfl_xor_sync(0xffffffffu, pk, 1);                                    \
        po += __shfl_xor_sync(0xffffffffu, po, 2);                                    \
        pk += __shfl_xor_sync(0xffffffffu, pk, 2);                                    \
        po += __shfl_xor_sync(0xffffffffu, po, 4);                                    \
        pk += __shfl_xor_sync(0xffffffffu, pk, 4);                                    \
        const float dv = s[RB][128 + d] - pk;                                         \
        const float bdv = sb * dv;                                                    \
        Mreg[0] = fmaf(bdv, kv0.x, Mreg[0]);                                          \
        Mreg[1] = fmaf(bdv, kv0.y, Mreg[1]);                                          \
        Mreg[2] = fmaf(bdv, kv0.z, Mreg[2]);                                          \
        Mreg[3] = fmaf(bdv, kv0.w, Mreg[3]);                                          \
        Mreg[4] = fmaf(bdv, kv1.x, Mreg[4]);                                          \
        Mreg[5] = fmaf(bdv, kv1.y, Mreg[5]);                                          \
        Mreg[6] = fmaf(bdv, kv1.z, Mreg[6]);                                          \
        Mreg[7] = fmaf(bdv, kv1.w, Mreg[7]);                                          \
        if (cg == 0)                                                                  \
            g_OG[(rbase + (STEP)) * CC + h * DD + d] = tf32r(s[RB][192 + d] * po);    \
    }

#define WINDOW(J, RB0, RB1, WB0, WB1, SFA, SFB, SBA, SBB, LFA, LFB, LBA, LBB)         \
    {                                                                                 \
        int ls = 2 * (J) + 8; if (ls > TT - 2) ls = TT - 2;                           \
        LFA = src[(rbase + ls) * NFUSE];                                              \
        LFB = src[(rbase + ls + 1) * NFUSE];                                          \
        if (t == 0) {                                                                 \
            LBA = g_Beta[(rbase + ls) * HH + h];                                      \
            LBB = g_Beta[(rbase + ls + 1) * HH + h];                                  \
        }                                                                             \
        s[WB0][t] = SFA; s[WB1][t] = SFB;                                             \
        if (t == 0) { sbv[WB0] = SBA; sbv[WB1] = SBB; }                               \
        SCAN_STEP(2 * (J),     RB0);                                                  \
        SCAN_STEP(2 * (J) + 1, RB1);                                                  \
        __syncthreads();                                                              \
    }

    for (int m = 0; m < TT / 8; m++) {
        const int j0 = 4 * m;
        WINDOW(j0 + 0, 0, 1, 2, 3, f1a, f1b, b1a, b1b, f0a, f0b, b0a, b0b);
        WINDOW(j0 + 1, 2, 3, 0, 1, f2a, f2b, b2a, b2b, f1a, f1b, b1a, b1b);
        WINDOW(j0 + 2, 0, 1, 2, 3, f3a, f3b, b3a, b3b, f2a, f2b, b2a, b2b);
        WINDOW(j0 + 3, 2, 3, 0, 1, f0a, f0b, b0a, b0b, f3a, f3b, b3a, b3b);
    }
#undef WINDOW
#undef SCAN_STEP
}

// ---------------------------------------------------------------------------
extern "C" void kernel_launch(void* const* d_in, const int* in_sizes, int n_in,
                              void* d_out, int out_size)
{
    const float* x     = (const float*)d_in[0];
    const float* Wq    = (const float*)d_in[1];
    const float* Wk    = (const float*)d_in[2];
    const float* Wv    = (const float*)d_in[3];
    const float* Wbeta = (const float*)d_in[4];
    const float* bbeta = (const float*)d_in[5];
    const float* Wgate = (const float*)d_in[6];
    const float* Wo    = (const float*)d_in[7];
    float* out = (float*)d_out;

    float *QKVGp, *OGp, *Bp, *xtp, *wtp;
    cudaGetSymbolAddress((void**)&QKVGp, g_QKVG);
    cudaGetSymbolAddress((void**)&OGp,   g_OG);
    cudaGetSymbolAddress((void**)&Bp,    g_Beta);
    cudaGetSymbolAddress((void**)&xtp,   g_xt);
    cudaGetSymbolAddress((void**)&wtp,   g_wt);

    cudaFuncSetAttribute(mma_gemm, cudaFuncAttributeMaxDynamicSharedMemorySize, GEMM_SMEM);

    const int WSZ = CC * CC;

    tf32_round_kernel<<<MROWS * CC / 4 / 256, 256>>>(x, xtp);
    wround_kernel<<<5 * WSZ / 4 / 256, 256>>>(Wq, Wk, Wv, Wgate, Wo, wtp);

    dim3 fgrid(NFUSE / 128, MROWS / 128);
    mma_gemm<<<fgrid, 256, GEMM_SMEM>>>(xtp, wtp, QKVGp, NFUSE, 3 * CC);

    beta_kernel<<<MROWS, 512>>>(x, Wbeta, bbeta, Bp);
    norm_kernel<<<(2 * MROWS * HH) / 8, 256>>>();
    scan_kernel<<<2 * BB * HH, 256>>>();

    dim3 ogrid(CC / 128, MROWS / 128);
    mma_gemm<<<ogrid, 256, GEMM_SMEM>>>(OGp, wtp + 4 * WSZ, out, CC, 1 << 30);
}

// round 14
// speedup vs baseline: 2.0071x; 1.0806x over previous
#include <cuda_runtime.h>
#include <cuda_bf16.h>
#include <math.h>
#include <stdint.h>

// Problem dims (fixed)
#define BB 4
#define TT 2048
#define CC 1024
#define HH 16
#define DD 64
#define MROWS (BB*TT)          // 8192
#define NFUSE 4096             // Q|K|V|G fused width

// ---------------------------------------------------------------------------
// Device scratch (cudaMalloc banned)
// ---------------------------------------------------------------------------
__device__ float g_QKVG[MROWS*NFUSE];     // fused Q|K|V|G, row stride 4096
__device__ float g_OG[MROWS*CC];          // tf32-rounded gate*o
__device__ float g_Beta[MROWS*HH];
__device__ float g_xt[MROWS*CC];          // tf32-rounded x
__device__ float g_wt[5*CC*CC];           // tf32-rounded Wq|Wk|Wv|Wgate|Wo

// ---------------------------------------------------------------------------
// PTX helpers (base-ISA only: mma.sync / ldmatrix / cp.async / cvt.tf32)
// ---------------------------------------------------------------------------
__device__ __forceinline__ uint32_t smem_u32(const void* p) {
    uint32_t a;
    asm("{ .reg .u64 t; cvta.to.shared.u64 t, %1; cvt.u32.u64 %0, t; }" : "=r"(a) : "l"(p));
    return a;
}
__device__ __forceinline__ void cp16(uint32_t dst, const void* src) {
    asm volatile("cp.async.cg.shared.global [%0], [%1], 16;" :: "r"(dst), "l"(src));
}
#define CP_COMMIT() asm volatile("cp.async.commit_group;" ::: "memory")
#define CP_WAIT1()  asm volatile("cp.async.wait_group 1;" ::: "memory")
#define CP_WAIT0()  asm volatile("cp.async.wait_group 0;" ::: "memory")

__device__ __forceinline__ void ldm_x4(uint32_t* r, uint32_t addr) {
    asm volatile("ldmatrix.sync.aligned.m8n8.x4.shared.b16 {%0,%1,%2,%3}, [%4];"
        : "=r"(r[0]), "=r"(r[1]), "=r"(r[2]), "=r"(r[3]) : "r"(addr));
}
__device__ __forceinline__ void mma1688(float* d, uint32_t a0, uint32_t a1,
                                        uint32_t a2, uint32_t a3,
                                        uint32_t b0, uint32_t b1) {
    asm volatile("mma.sync.aligned.m16n8k8.row.col.f32.tf32.tf32.f32 "
        "{%0,%1,%2,%3}, {%4,%5,%6,%7}, {%8,%9}, {%0,%1,%2,%3};"
        : "+f"(d[0]), "+f"(d[1]), "+f"(d[2]), "+f"(d[3])
        : "r"(a0), "r"(a1), "r"(a2), "r"(a3), "r"(b0), "r"(b1));
}
__device__ __forceinline__ float tf32r(float x) {
    float r;
    asm("cvt.rna.tf32.f32 %0, %1;" : "=f"(r) : "f"(x));
    return r;
}

// ---------------------------------------------------------------------------
// fp32 -> tf32-rounded fp32 (unbiased), float4-vectorized
// ---------------------------------------------------------------------------
__global__ __launch_bounds__(256)
void tf32_round_kernel(const float* __restrict__ in, float* __restrict__ out)
{
    const int i = blockIdx.x * 256 + threadIdx.x;
    float4 v = ((const float4*)in)[i];
    v.x = tf32r(v.x); v.y = tf32r(v.y); v.z = tf32r(v.z); v.w = tf32r(v.w);
    ((float4*)out)[i] = v;
}

__global__ __launch_bounds__(256)
void wround_kernel(const float* __restrict__ w0, const float* __restrict__ w1,
                   const float* __restrict__ w2, const float* __restrict__ w3,
                   const float* __restrict__ w4, float* __restrict__ out)
{
    const int i = blockIdx.x * 256 + threadIdx.x;       // float4 index, 5*WSZ/4
    const int per = (CC * CC) / 4;
    const int which = i / per;
    const int local = i - which * per;
    const float* src = (which == 0) ? w0 : (which == 1) ? w1 :
                       (which == 2) ? w2 : (which == 3) ? w3 : w4;
    float4 v = ((const float4*)src)[local];
    v.x = tf32r(v.x); v.y = tf32r(v.y); v.z = tf32r(v.z); v.w = tf32r(v.w);
    ((float4*)out)[i] = v;
}

// ---------------------------------------------------------------------------
// TF32 HMMA GEMM (unchanged — verified passing, at tf32 mma floor)
// ---------------------------------------------------------------------------
#define STG_B 32768
#define NSTG  3
#define GEMM_SMEM (NSTG*STG_B)   // 96 KB

__global__ __launch_bounds__(256, 2)
void mma_gemm(const float* __restrict__ Ag, const float* __restrict__ Bg,
              float* __restrict__ Cc, int ldc, int sig_start)
{
    extern __shared__ char smem[];
    const uint32_t sbase = smem_u32(smem);
    const int tid = threadIdx.x;
    const int lane = tid & 31;
    const int wid = tid >> 5;
    const int m_blk = blockIdx.y * 128;
    const int n_blk = blockIdx.x * 128;
    const int warp_m = (wid >> 2) * 64;
    const int warp_n = (wid & 3) * 32;

    const char* pA = (const char*)(Ag + (size_t)m_blk * CC);
    const char* pB = (const char*)(Bg + (size_t)n_blk * CC);

#define LOAD_STAGE(KT, STG) do {                                               \
    const uint32_t sb_ = sbase + (STG) * STG_B;                                \
    const int k0b_ = (KT) * 128;                                               \
    _Pragma("unroll")                                                          \
    for (int j = 0; j < 4; j++) {                                              \
        const int c_ = j * 256 + tid;                                          \
        const int r_ = c_ >> 3, q_ = c_ & 7;                                   \
        const uint32_t so_ = (uint32_t)(r_ * 128 + ((q_ ^ (r_ & 7)) * 16));    \
        const size_t go_ = (size_t)r_ * 4096 + k0b_ + q_ * 16;                 \
        cp16(sb_ + 0     + so_, pA + go_);                                     \
        cp16(sb_ + 16384 + so_, pB + go_);                                     \
    }                                                                          \
    CP_COMMIT();                                                               \
} while (0)

    float acc[4][4][4];
#pragma unroll
    for (int a = 0; a < 4; a++)
#pragma unroll
        for (int b = 0; b < 4; b++)
#pragma unroll
            for (int c = 0; c < 4; c++) acc[a][b][c] = 0.0f;

    const int trow = lane & 7;
    const int tile = lane >> 3;
    const int a_row_add = trow + (tile & 1) * 8;
    const int a_chk_add = tile >> 1;
    const int b_row_add = trow + (tile >> 1) * 8;
    const int b_chk_add = tile & 1;

    LOAD_STAGE(0, 0);
    LOAD_STAGE(1, 1);

    for (int kt = 0; kt < 32; kt++) {
        if (kt + 1 < 32) CP_WAIT1(); else CP_WAIT0();
        __syncthreads();
        const uint32_t st = sbase + (kt % NSTG) * STG_B;

#pragma unroll
        for (int ks = 0; ks < 4; ks++) {
            const int ckbase = 2 * ks;
            uint32_t bfr[2][4];
#pragma unroll
            for (int bi = 0; bi < 2; bi++) {
                const int row = warp_n + bi * 16 + b_row_add;
                const uint32_t q = (uint32_t)((ckbase + b_chk_add) ^ (row & 7));
                ldm_x4(bfr[bi], st + 16384 + (uint32_t)row * 128 + q * 16);
            }
#pragma unroll
            for (int mi = 0; mi < 4; mi++) {
                const int row = warp_m + mi * 16 + a_row_add;
                const uint32_t q = (uint32_t)((ckbase + a_chk_add) ^ (row & 7));
                uint32_t af[4];
                ldm_x4(af, st + (uint32_t)row * 128 + q * 16);
#pragma unroll
                for (int ni = 0; ni < 4; ni++) {
                    uint32_t* bp = &bfr[ni >> 1][(ni & 1) * 2];
                    mma1688(acc[mi][ni], af[0], af[1], af[2], af[3], bp[0], bp[1]);
                }
            }
        }
        __syncthreads();
        if (kt + 2 < 32) LOAD_STAGE(kt + 2, (kt + 2) % NSTG);
    }
#undef LOAD_STAGE

    const int er = lane >> 2;
    const int ec = (lane & 3) * 2;
#pragma unroll
    for (int mi = 0; mi < 4; mi++) {
        const int row = m_blk + warp_m + mi * 16 + er;
#pragma unroll
        for (int ni = 0; ni < 4; ni++) {
            const int col = n_blk + warp_n + ni * 8 + ec;
            float v0 = acc[mi][ni][0], v1 = acc[mi][ni][1];
            float v2 = acc[mi][ni][2], v3 = acc[mi][ni][3];
            if (col >= sig_start) {
                v0 = 1.0f / (1.0f + expf(-v0));
                v1 = 1.0f / (1.0f + expf(-v1));
                v2 = 1.0f / (1.0f + expf(-v2));
                v3 = 1.0f / (1.0f + expf(-v3));
            }
            float2 lo2 = {v0, v1}, hi2 = {v2, v3};
            *(float2*)&Cc[(size_t)row * ldc + col] = lo2;
            *(float2*)&Cc[(size_t)(row + 8) * ldc + col] = hi2;
        }
    }
}

// ---------------------------------------------------------------------------
// beta = sigmoid(x @ Wbeta^T + bbeta) : (8192, 16)
// 512 blocks x (16 rows, 16 heads). Warp w owns head w: W row in registers
// (8 float4), x rows staged in smem once per block. W traffic 512MB -> 32MB.
// ---------------------------------------------------------------------------
__global__ __launch_bounds__(512)
void beta_kernel(const float* __restrict__ x, const float* __restrict__ Wb,
                 const float* __restrict__ bb, float* __restrict__ Beta)
{
    __shared__ __align__(16) float xs[16][CC];
    const int tid = threadIdx.x;
    const int r0 = blockIdx.x * 16;

    // stage 16 x rows (64KB): 512 threads x 32 floats (8 float4)
    {
        const float4* xg = (const float4*)&x[(size_t)r0 * CC];
        float4* xs4 = (float4*)xs;
#pragma unroll
        for (int j = 0; j < 8; j++)
            xs4[j * 512 + tid] = xg[j * 512 + tid];
    }
    __syncthreads();

    const int h = tid >> 5;          // head = warp
    const int lane = tid & 31;
    const float4* w4 = (const float4*)&Wb[(size_t)h * CC];
    float4 wreg[8];
#pragma unroll
    for (int i = 0; i < 8; i++) wreg[i] = w4[i * 32 + lane];
    const float bias = bb[h];

#pragma unroll
    for (int r = 0; r < 16; r++) {
        const float4* x4 = (const float4*)xs[r];
        float accA = 0.0f, accB = 0.0f;
#pragma unroll
        for (int i = 0; i < 8; i += 2) {
            float4 a0 = x4[(i + 0) * 32 + lane];
            float4 a1 = x4[(i + 1) * 32 + lane];
            accA = fmaf(a0.x, wreg[i].x, accA);
            accA = fmaf(a0.y, wreg[i].y, accA);
            accA = fmaf(a0.z, wreg[i].z, accA);
            accA = fmaf(a0.w, wreg[i].w, accA);
            accB = fmaf(a1.x, wreg[i + 1].x, accB);
            accB = fmaf(a1.y, wreg[i + 1].y, accB);
            accB = fmaf(a1.z, wreg[i + 1].z, accB);
            accB = fmaf(a1.w, wreg[i + 1].w, accB);
        }
        float acc = accA + accB;
#pragma unroll
        for (int off = 16; off > 0; off >>= 1)
            acc += __shfl_xor_sync(0xffffffffu, acc, off);
        if (lane == 0) {
            float v = acc + bias;
            Beta[(size_t)(r0 + r) * HH + h] = 1.0f / (1.0f + expf(-v));
        }
    }
}

// ---------------------------------------------------------------------------
// L2-normalize Q and K per (row, head) over D=64 (in fused QKVG buffer)
// ---------------------------------------------------------------------------
__global__ __launch_bounds__(256)
void norm_kernel()
{
    const int gw = blockIdx.x * 8 + (threadIdx.x >> 5);
    const int lane = threadIdx.x & 31;
    const int which = gw & 1;
    const int rem = gw >> 1;
    const int row = rem >> 4;
    const int h = rem & 15;
    float* p = &g_QKVG[(size_t)row * NFUSE + which * CC + h * DD];
    float v0 = p[lane];
    float v1 = p[lane + 32];
    float s = v0 * v0 + v1 * v1;
#pragma unroll
    for (int off = 16; off > 0; off >>= 1)
        s += __shfl_xor_sync(0xffffffffu, s, off);
    float n = sqrtf(s);
    float scale = 1.0f / fmaxf(n, 1e-12f);
    p[lane]      = v0 * scale;
    p[lane + 32] = v1 * scale;
}

// ---------------------------------------------------------------------------
// Delta-rule scan, ROW-SPLIT + 2-STEP FUSED (WY-2).
// 2 CTAs per (b,h) (rows 0-31 / 32-63), 256 threads, 8 threads/row.
// Per window: 6 dots against a SINGLE M traversal (M.q1, M.k1, M.q2, M.k2,
// k1.k2, k1.q2), batched 3-level shfl reduce, exact algebraic fixups:
//   dv1 = v1 - M.k1;              bd1 = b1*dv1
//   pk2' = M.k2 + bd1*(k1.k2);    dv2 = v2 - pk2';   bd2 = b2*dv2
//   po2' = M.q2 + bd1*(k1.q2)     (pre-update state at t+1)
//   M += bd1 k1^T + bd2 k2^T
// One reduce-latency per 2 steps instead of per step.
// ---------------------------------------------------------------------------
__global__ __launch_bounds__(256, 1)
void scan_kernel()
{
    const int bh = blockIdx.x >> 1;
    const int half = blockIdx.x & 1;
    const int b = bh >> 4;
    const int h = bh & 15;
    __shared__ __align__(16) float s[4][256];  // [0:64)q [64:128)k [128:192)v [192:256)g
    __shared__ float sbv[4];

    const int t = threadIdx.x;
    const int d = half * 32 + (t >> 3);   // global row 0..63
    const int cg = t & 7;                 // column group (8 cols)
    const int cbase = cg * 8;

    const int arr = t >> 6;               // loader quarter: 0=q 1=k 2=v 3=g
    const int idx = t & 63;
    const float* src = g_QKVG + (size_t)arr * CC + (size_t)h * DD + idx;
    const size_t rbase = (size_t)b * TT;

    float Mreg[8];
#pragma unroll
    for (int j = 0; j < 8; j++) Mreg[j] = 0.0f;

    // register queue slots 0..3 hold pairs 0..3 (steps 0..7)
    float f0a = src[(rbase + 0) * NFUSE], f0b = src[(rbase + 1) * NFUSE];
    float f1a = src[(rbase + 2) * NFUSE], f1b = src[(rbase + 3) * NFUSE];
    float f2a = src[(rbase + 4) * NFUSE], f2b = src[(rbase + 5) * NFUSE];
    float f3a = src[(rbase + 6) * NFUSE], f3b = src[(rbase + 7) * NFUSE];
    float b0a = 0, b0b = 0, b1a = 0, b1b = 0, b2a = 0, b2b = 0, b3a = 0, b3b = 0;
    if (t == 0) {
        b0a = g_Beta[(rbase + 0) * HH + h]; b0b = g_Beta[(rbase + 1) * HH + h];
        b1a = g_Beta[(rbase + 2) * HH + h]; b1b = g_Beta[(rbase + 3) * HH + h];
        b2a = g_Beta[(rbase + 4) * HH + h]; b2b = g_Beta[(rbase + 5) * HH + h];
        b3a = g_Beta[(rbase + 6) * HH + h]; b3b = g_Beta[(rbase + 7) * HH + h];
    }
    s[0][t] = f0a; s[1][t] = f0b;
    if (t == 0) { sbv[0] = b0a; sbv[1] = b0b; }
    __syncthreads();

    // fused 2-step body: step STEP from buffer RB0, step STEP+1 from RB1
#define SCAN_STEP2(STEP, RB0, RB1)                                                    \
    {                                                                                 \
        const float4* q1p = (const float4*)&s[RB0][cbase];                            \
        const float4* k1p = (const float4*)&s[RB0][64 + cbase];                       \
        const float4* q2p = (const float4*)&s[RB1][cbase];                            \
        const float4* k2p = (const float4*)&s[RB1][64 + cbase];                       \
        const float b1s = sbv[RB0], b2s = sbv[RB1];                                   \
        float4 q1a = q1p[0], q1b = q1p[1];                                            \
        float4 k1a = k1p[0], k1b = k1p[1];                                            \
        float4 q2a = q2p[0], q2b = q2p[1];                                            \
        float4 k2a = k2p[0], k2b = k2p[1];                                            \
        float po1 = 0, pk1 = 0, po2 = 0, pk2 = 0, ck = 0, cq = 0;                     \
        po1 = fmaf(Mreg[0], q1a.x, po1); po1 = fmaf(Mreg[1], q1a.y, po1);             \
        po1 = fmaf(Mreg[2], q1a.z, po1); po1 = fmaf(Mreg[3], q1a.w, po1);             \
        po1 = fmaf(Mreg[4], q1b.x, po1); po1 = fmaf(Mreg[5], q1b.y, po1);             \
        po1 = fmaf(Mreg[6], q1b.z, po1); po1 = fmaf(Mreg[7], q1b.w, po1);             \
        pk1 = fmaf(Mreg[0], k1a.x, pk1); pk1 = fmaf(Mreg[1], k1a.y, pk1);             \
        pk1 = fmaf(Mreg[2], k1a.z, pk1); pk1 = fmaf(Mreg[3], k1a.w, pk1);             \
        pk1 = fmaf(Mreg[4], k1b.x, pk1); pk1 = fmaf(Mreg[5], k1b.y, pk1);             \
        pk1 = fmaf(Mreg[6], k1b.z, pk1); pk1 = fmaf(Mreg[7], k1b.w, pk1);             \
        po2 = fmaf(Mreg[0], q2a.x, po2); po2 = fmaf(Mreg[1], q2a.y, po2);             \
        po2 = fmaf(Mreg[2], q2a.z, po2); po2 = fmaf(Mreg[3], q2a.w, po2);             \
        po2 = fmaf(Mreg[4], q2b.x, po2); po2 = fmaf(Mreg[5], q2b.y, po2);             \
        po2 = fmaf(Mreg[6], q2b.z, po2); po2 = fmaf(Mreg[7], q2b.w, po2);             \
        pk2 = fmaf(Mreg[0], k2a.x, pk2); pk2 = fmaf(Mreg[1], k2a.y, pk2);             \
        pk2 = fmaf(Mreg[2], k2a.z, pk2); pk2 = fmaf(Mreg[3], k2a.w, pk2);             \
        pk2 = fmaf(Mreg[4], k2b.x, pk2); pk2 = fmaf(Mreg[5], k2b.y, pk2);             \
        pk2 = fmaf(Mreg[6], k2b.z, pk2); pk2 = fmaf(Mreg[7], k2b.w, pk2);             \
        ck = fmaf(k1a.x, k2a.x, ck); ck = fmaf(k1a.y, k2a.y, ck);                     \
        ck = fmaf(k1a.z, k2a.z, ck); ck = fmaf(k1a.w, k2a.w, ck);                     \
        ck = fmaf(k1b.x, k2b.x, ck); ck = fmaf(k1b.y, k2b.y, ck);                     \
        ck = fmaf(k1b.z, k2b.z, ck); ck = fmaf(k1b.w, k2b.w, ck);                     \
        cq = fmaf(k1a.x, q2a.x, cq); cq = fmaf(k1a.y, q2a.y, cq);                     \
        cq = fmaf(k1a.z, q2a.z, cq); cq = fmaf(k1a.w, q2a.w, cq);                     \
        cq = fmaf(k1b.x, q2b.x, cq); cq = fmaf(k1b.y, q2b.y, cq);                     \
        cq = fmaf(k1b.z, q2b.z, cq); cq = fmaf(k1b.w, q2b.w, cq);                     \
        _Pragma("unroll")                                                             \
        for (int off = 1; off <= 4; off <<= 1) {                                      \
            po1 += __shfl_xor_sync(0xffffffffu, po1, off);                            \
            pk1 += __shfl_xor_sync(0xffffffffu, pk1, off);                            \
            po2 += __shfl_xor_sync(0xffffffffu, po2, off);                            \
            pk2 += __shfl_xor_sync(0xffffffffu, pk2, off);                            \
            ck  += __shfl_xor_sync(0xffffffffu, ck,  off);                            \
            cq  += __shfl_xor_sync(0xffffffffu, cq,  off);                            \
        }                                                                             \
        const float dv1 = s[RB0][128 + d] - pk1;                                      \
        const float bd1 = b1s * dv1;                                                  \
        const float pk2c = fmaf(bd1, ck, pk2);                                        \
        const float dv2 = s[RB1][128 + d] - pk2c;                                     \
        const float bd2 = b2s * dv2;                                                  \
        const float po2c = fmaf(bd1, cq, po2);                                        \
        Mreg[0] = fmaf(bd2, k2a.x, fmaf(bd1, k1a.x, Mreg[0]));                        \
        Mreg[1] = fmaf(bd2, k2a.y, fmaf(bd1, k1a.y, Mreg[1]));                        \
        Mreg[2] = fmaf(bd2, k2a.z, fmaf(bd1, k1a.z, Mreg[2]));                        \
        Mreg[3] = fmaf(bd2, k2a.w, fmaf(bd1, k1a.w, Mreg[3]));                        \
        Mreg[4] = fmaf(bd2, k2b.x, fmaf(bd1, k1b.x, Mreg[4]));                        \
        Mreg[5] = fmaf(bd2, k2b.y, fmaf(bd1, k1b.y, Mreg[5]));                        \
        Mreg[6] = fmaf(bd2, k2b.z, fmaf(bd1, k1b.z, Mreg[6]));                        \
        Mreg[7] = fmaf(bd2, k2b.w, fmaf(bd1, k1b.w, Mreg[7]));                        \
        if (cg == 0) {                                                                \
            g_OG[(rbase + (STEP))     * CC + h * DD + d] = tf32r(s[RB0][192 + d] * po1);  \
            g_OG[(rbase + (STEP) + 1) * CC + h * DD + d] = tf32r(s[RB1][192 + d] * po2c); \
        }                                                                             \
    }

#define WINDOW(J, RB0, RB1, WB0, WB1, SFA, SFB, SBA, SBB, LFA, LFB, LBA, LBB)         \
    {                                                                                 \
        int ls = 2 * (J) + 8; if (ls > TT - 2) ls = TT - 2;                           \
        LFA = src[(rbase + ls) * NFUSE];                                              \
        LFB = src[(rbase + ls + 1) * NFUSE];                                          \
        if (t == 0) {                                                                 \
            LBA = g_Beta[(rbase + ls) * HH + h];                                      \
            LBB = g_Beta[(rbase + ls + 1) * HH + h];                                  \
        }                                                                             \
        s[WB0][t] = SFA; s[WB1][t] = SFB;                                             \
        if (t == 0) { sbv[WB0] = SBA; sbv[WB1] = SBB; }                               \
        SCAN_STEP2(2 * (J), RB0, RB1);                                                \
        __syncthreads();                                                              \
    }

    for (int m = 0; m < TT / 8; m++) {
        const int j0 = 4 * m;
        WINDOW(j0 + 0, 0, 1, 2, 3, f1a, f1b, b1a, b1b, f0a, f0b, b0a, b0b);
        WINDOW(j0 + 1, 2, 3, 0, 1, f2a, f2b, b2a, b2b, f1a, f1b, b1a, b1b);
        WINDOW(j0 + 2, 0, 1, 2, 3, f3a, f3b, b3a, b3b, f2a, f2b, b2a, b2b);
        WINDOW(j0 + 3, 2, 3, 0, 1, f0a, f0b, b0a, b0b, f3a, f3b, b3a, b3b);
    }
#undef WINDOW
#undef SCAN_STEP2
}

// ---------------------------------------------------------------------------
extern "C" void kernel_launch(void* const* d_in, const int* in_sizes, int n_in,
                              void* d_out, int out_size)
{
    const float* x     = (const float*)d_in[0];
    const float* Wq    = (const float*)d_in[1];
    const float* Wk    = (const float*)d_in[2];
    const float* Wv    = (const float*)d_in[3];
    const float* Wbeta = (const float*)d_in[4];
    const float* bbeta = (const float*)d_in[5];
    const float* Wgate = (const float*)d_in[6];
    const float* Wo    = (const float*)d_in[7];
    float* out = (float*)d_out;

    float *QKVGp, *OGp, *Bp, *xtp, *wtp;
    cudaGetSymbolAddress((void**)&QKVGp, g_QKVG);
    cudaGetSymbolAddress((void**)&OGp,   g_OG);
    cudaGetSymbolAddress((void**)&Bp,    g_Beta);
    cudaGetSymbolAddress((void**)&xtp,   g_xt);
    cudaGetSymbolAddress((void**)&wtp,   g_wt);

    cudaFuncSetAttribute(mma_gemm, cudaFuncAttributeMaxDynamicSharedMemorySize, GEMM_SMEM);

    const int WSZ = CC * CC;

    tf32_round_kernel<<<MROWS * CC / 4 / 256, 256>>>(x, xtp);
    wround_kernel<<<5 * WSZ / 4 / 256, 256>>>(Wq, Wk, Wv, Wgate, Wo, wtp);

    dim3 fgrid(NFUSE / 128, MROWS / 128);
    mma_gemm<<<fgrid, 256, GEMM_SMEM>>>(xtp, wtp, QKVGp, NFUSE, 3 * CC);

    beta_kernel<<<MROWS / 16, 512>>>(x, Wbeta, bbeta, Bp);
    norm_kernel<<<(2 * MROWS * HH) / 8, 256>>>();
    scan_kernel<<<2 * BB * HH, 256>>>();

    dim3 ogrid(CC / 128, MROWS / 128);
    mma_gemm<<<ogrid, 256, GEMM_SMEM>>>(OGp, wtp + 4 * WSZ, out, CC, 1 << 30);
}

// round 16
// speedup vs baseline: 2.5323x; 1.2617x over previous
#include <cuda_runtime.h>
#include <cuda_fp16.h>
#include <math.h>
#include <stdint.h>

// Problem dims (fixed)
#define BB 4
#define TT 2048
#define CC 1024
#define HH 16
#define DD 64
#define MROWS (BB*TT)          // 8192
#define NFUSE 4096             // Q|K|V|G fused width
#define WSCALE 64.0f
#define WINV   (1.0f/64.0f)

// ---------------------------------------------------------------------------
// Device scratch (cudaMalloc banned)
// ---------------------------------------------------------------------------
__device__ float g_QKVG[MROWS*NFUSE];     // fused Q|K|V|G fp32, row stride 4096
__device__ float g_Beta[MROWS*HH];
__device__ __half g_xh[MROWS*CC];         // fp16 x
__device__ __half g_wh[5*CC*CC];          // fp16 64*W (Wq|Wk|Wv|Wgate|Wo)
__device__ __half g_OGh[MROWS*CC];        // fp16 gate*o

// ---------------------------------------------------------------------------
// PTX helpers (base-ISA only: mma.sync / ldmatrix / cp.async)
// ---------------------------------------------------------------------------
__device__ __forceinline__ uint32_t smem_u32(const void* p) {
    uint32_t a;
    asm("{ .reg .u64 t; cvta.to.shared.u64 t, %1; cvt.u32.u64 %0, t; }" : "=r"(a) : "l"(p));
    return a;
}
__device__ __forceinline__ void cp16(uint32_t dst, const void* src) {
    asm volatile("cp.async.cg.shared.global [%0], [%1], 16;" :: "r"(dst), "l"(src));
}
#define CP_COMMIT() asm volatile("cp.async.commit_group;" ::: "memory")
#define CP_WAIT1()  asm volatile("cp.async.wait_group 1;" ::: "memory")
#define CP_WAIT0()  asm volatile("cp.async.wait_group 0;" ::: "memory")

__device__ __forceinline__ void ldm_x4(uint32_t* r, uint32_t addr) {
    asm volatile("ldmatrix.sync.aligned.m8n8.x4.shared.b16 {%0,%1,%2,%3}, [%4];"
        : "=r"(r[0]), "=r"(r[1]), "=r"(r[2]), "=r"(r[3]) : "r"(addr));
}
// fp16 mma, fp32 accumulate
__device__ __forceinline__ void mma_f16(float* d, const uint32_t* a, const uint32_t* b) {
    asm volatile("mma.sync.aligned.m16n8k16.row.col.f32.f16.f16.f32 "
        "{%0,%1,%2,%3}, {%4,%5,%6,%7}, {%8,%9}, {%0,%1,%2,%3};"
        : "+f"(d[0]), "+f"(d[1]), "+f"(d[2]), "+f"(d[3])
        : "r"(a[0]), "r"(a[1]), "r"(a[2]), "r"(a[3]), "r"(b[0]), "r"(b[1]));
}

// ---------------------------------------------------------------------------
// fp32 -> fp16 conversion (optional scale), float4-vectorized
// ---------------------------------------------------------------------------
__global__ __launch_bounds__(256)
void h_conv_kernel(const float* __restrict__ in, __half* __restrict__ out, float scale)
{
    const int i = blockIdx.x * 256 + threadIdx.x;
    float4 v = ((const float4*)in)[i];
    __half2 lo = __floats2half2_rn(v.x * scale, v.y * scale);
    __half2 hi = __floats2half2_rn(v.z * scale, v.w * scale);
    ((__half2*)out)[2 * i + 0] = lo;
    ((__half2*)out)[2 * i + 1] = hi;
}

// all five weights in one launch (scaled by WSCALE)
__global__ __launch_bounds__(256)
void whalf_kernel(const float* __restrict__ w0, const float* __restrict__ w1,
                  const float* __restrict__ w2, const float* __restrict__ w3,
                  const float* __restrict__ w4, __half* __restrict__ out)
{
    const int i = blockIdx.x * 256 + threadIdx.x;       // float4 index
    const int per = (CC * CC) / 4;
    const int which = i / per;
    const int local = i - which * per;
    const float* src = (which == 0) ? w0 : (which == 1) ? w1 :
                       (which == 2) ? w2 : (which == 3) ? w3 : w4;
    float4 v = ((const float4*)src)[local];
    __half2 lo = __floats2half2_rn(v.x * WSCALE, v.y * WSCALE);
    __half2 hi = __floats2half2_rn(v.z * WSCALE, v.w * WSCALE);
    ((__half2*)out)[2 * i + 0] = lo;
    ((__half2*)out)[2 * i + 1] = hi;
}

// ---------------------------------------------------------------------------
// FP16 HMMA GEMM: C[8192,N] = (1/64) * A[8192,1024] @ B[N,1024]^T
// A fp16 (unscaled), B fp16 (64x-scaled). fp32 in/out epilogue with 1/64.
// CTA tile 128x128, BK=64, 3-stage cp.async, 96KB smem -> 2 CTAs/SM.
// 8 warps (2x4), warp tile 64x32. Sigmoid (after unscale) for col>=sig_start.
// SMEM stage (32KB): A[128][64]h @0, B[128][64]h @16K; rows = 128B,
// 16B-chunk swizzle phys_q = q ^ (row&7)  (verified layout from R5 bf16).
// ---------------------------------------------------------------------------
#define STG_B 32768
#define NSTG  3
#define GEMM_SMEM (NSTG*STG_B)   // 96 KB

__global__ __launch_bounds__(256, 2)
void hgemm(const __half* __restrict__ Ag, const __half* __restrict__ Bg,
           float* __restrict__ Cc, int ldc, int sig_start)
{
    extern __shared__ char smem[];
    const uint32_t sbase = smem_u32(smem);
    const int tid = threadIdx.x;
    const int lane = tid & 31;
    const int wid = tid >> 5;
    const int m_blk = blockIdx.y * 128;
    const int n_blk = blockIdx.x * 128;
    const int warp_m = (wid >> 2) * 64;
    const int warp_n = (wid & 3) * 32;

    const char* pA = (const char*)(Ag + (size_t)m_blk * CC);
    const char* pB = (const char*)(Bg + (size_t)n_blk * CC);

    // per stage per matrix 16KB = 1024 x 16B chunks; 4 per thread
#define LOAD_STAGE(KT, STG) do {                                               \
    const uint32_t sb_ = sbase + (STG) * STG_B;                                \
    const int k0b_ = (KT) * 128;   /* 64 fp16 = 128 bytes */                   \
    _Pragma("unroll")                                                          \
    for (int j = 0; j < 4; j++) {                                              \
        const int c_ = j * 256 + tid;                                          \
        const int r_ = c_ >> 3, q_ = c_ & 7;                                   \
        const uint32_t so_ = (uint32_t)(r_ * 128 + ((q_ ^ (r_ & 7)) * 16));    \
        const size_t go_ = (size_t)r_ * 2048 + k0b_ + q_ * 16;                 \
        cp16(sb_ + 0     + so_, pA + go_);                                     \
        cp16(sb_ + 16384 + so_, pB + go_);                                     \
    }                                                                          \
    CP_COMMIT();                                                               \
} while (0)

    float acc[4][4][4];
#pragma unroll
    for (int a = 0; a < 4; a++)
#pragma unroll
        for (int b = 0; b < 4; b++)
#pragma unroll
            for (int c = 0; c < 4; c++) acc[a][b][c] = 0.0f;

    // ldmatrix per-thread mapping (verified in R5)
    const int ra = (lane & 7) + (lane & 8);          // A row within 16
    const int ka = (lane >> 4) << 3;                 // A k offset 0/8
    const int rb = (lane & 7) + ((lane & 16) >> 1);  // B row within 16
    const int kb = lane & 8;                         // B k offset 0/8
    const int sw = lane & 7;

    LOAD_STAGE(0, 0);
    LOAD_STAGE(1, 1);

    for (int kt = 0; kt < 16; kt++) {
        if (kt + 1 < 16) CP_WAIT1(); else CP_WAIT0();
        __syncthreads();
        const uint32_t st = sbase + (kt % NSTG) * STG_B;

#pragma unroll
        for (int k16 = 0; k16 < 64; k16 += 16) {
            uint32_t bh[2][4];
#pragma unroll
            for (int bi = 0; bi < 2; bi++) {
                const int n0 = warp_n + bi * 16;
                const uint32_t addr = st + 16384 + ((uint32_t)(n0 + rb) << 7)
                                    + ((uint32_t)(((k16 + kb) >> 3) ^ sw) << 4);
                ldm_x4(bh[bi], addr);
            }
#pragma unroll
            for (int mi = 0; mi < 4; mi++) {
                const int m0 = warp_m + mi * 16;
                const uint32_t addr = st + ((uint32_t)(m0 + ra) << 7)
                                    + ((uint32_t)(((k16 + ka) >> 3) ^ sw) << 4);
                uint32_t ah[4];
                ldm_x4(ah, addr);
#pragma unroll
                for (int ni = 0; ni < 4; ni++) {
                    uint32_t* bp = &bh[ni >> 1][(ni & 1) * 2];
                    mma_f16(acc[mi][ni], ah, bp);
                }
            }
        }
        __syncthreads();
        if (kt + 2 < 16) LOAD_STAGE(kt + 2, (kt + 2) % NSTG);
    }
#undef LOAD_STAGE

    // epilogue: unscale by 1/64, optional sigmoid
    const int er = lane >> 2;
    const int ec = (lane & 3) * 2;
#pragma unroll
    for (int mi = 0; mi < 4; mi++) {
        const int row = m_blk + warp_m + mi * 16 + er;
#pragma unroll
        for (int ni = 0; ni < 4; ni++) {
            const int col = n_blk + warp_n + ni * 8 + ec;
            float v0 = acc[mi][ni][0] * WINV, v1 = acc[mi][ni][1] * WINV;
            float v2 = acc[mi][ni][2] * WINV, v3 = acc[mi][ni][3] * WINV;
            if (col >= sig_start) {
                v0 = 1.0f / (1.0f + expf(-v0));
                v1 = 1.0f / (1.0f + expf(-v1));
                v2 = 1.0f / (1.0f + expf(-v2));
                v3 = 1.0f / (1.0f + expf(-v3));
            }
            float2 lo2 = {v0, v1}, hi2 = {v2, v3};
            *(float2*)&Cc[(size_t)row * ldc + col] = lo2;
            *(float2*)&Cc[(size_t)(row + 8) * ldc + col] = hi2;
        }
    }
}

// ---------------------------------------------------------------------------
// beta = sigmoid(x @ Wbeta^T + bbeta) : (8192, 16)   (R14 version)
// ---------------------------------------------------------------------------
__global__ __launch_bounds__(512)
void beta_kernel(const float* __restrict__ x, const float* __restrict__ Wb,
                 const float* __restrict__ bb, float* __restrict__ Beta)
{
    __shared__ __align__(16) float xs[16][CC];
    const int tid = threadIdx.x;
    const int r0 = blockIdx.x * 16;

    {
        const float4* xg = (const float4*)&x[(size_t)r0 * CC];
        float4* xs4 = (float4*)xs;
#pragma unroll
        for (int j = 0; j < 8; j++)
            xs4[j * 512 + tid] = xg[j * 512 + tid];
    }
    __syncthreads();

    const int h = tid >> 5;
    const int lane = tid & 31;
    const float4* w4 = (const float4*)&Wb[(size_t)h * CC];
    float4 wreg[8];
#pragma unroll
    for (int i = 0; i < 8; i++) wreg[i] = w4[i * 32 + lane];
    const float bias = bb[h];

#pragma unroll
    for (int r = 0; r < 16; r++) {
        const float4* x4 = (const float4*)xs[r];
        float accA = 0.0f, accB = 0.0f;
#pragma unroll
        for (int i = 0; i < 8; i += 2) {
            float4 a0 = x4[(i + 0) * 32 + lane];
            float4 a1 = x4[(i + 1) * 32 + lane];
            accA = fmaf(a0.x, wreg[i].x, accA);
            accA = fmaf(a0.y, wreg[i].y, accA);
            accA = fmaf(a0.z, wreg[i].z, accA);
            accA = fmaf(a0.w, wreg[i].w, accA);
            accB = fmaf(a1.x, wreg[i + 1].x, accB);
            accB = fmaf(a1.y, wreg[i + 1].y, accB);
            accB = fmaf(a1.z, wreg[i + 1].z, accB);
            accB = fmaf(a1.w, wreg[i + 1].w, accB);
        }
        float acc = accA + accB;
#pragma unroll
        for (int off = 16; off > 0; off >>= 1)
            acc += __shfl_xor_sync(0xffffffffu, acc, off);
        if (lane == 0) {
            float v = acc + bias;
            Beta[(size_t)(r0 + r) * HH + h] = 1.0f / (1.0f + expf(-v));
        }
    }
}

// ---------------------------------------------------------------------------
// L2-normalize Q and K per (row, head) over D=64 (in fused QKVG buffer)
// ---------------------------------------------------------------------------
__global__ __launch_bounds__(256)
void norm_kernel()
{
    const int gw = blockIdx.x * 8 + (threadIdx.x >> 5);
    const int lane = threadIdx.x & 31;
    const int which = gw & 1;
    const int rem = gw >> 1;
    const int row = rem >> 4;
    const int h = rem & 15;
    float* p = &g_QKVG[(size_t)row * NFUSE + which * CC + h * DD];
    float v0 = p[lane];
    float v1 = p[lane + 32];
    float s = v0 * v0 + v1 * v1;
#pragma unroll
    for (int off = 16; off > 0; off >>= 1)
        s += __shfl_xor_sync(0xffffffffu, s, off);
    float n = sqrtf(s);
    float scale = 1.0f / fmaxf(n, 1e-12f);
    p[lane]      = v0 * scale;
    p[lane + 32] = v1 * scale;
}

// ---------------------------------------------------------------------------
// Delta-rule scan, ROW-SPLIT + WY-2 (R14, verified). Writes fp16 OG.
// ---------------------------------------------------------------------------
__global__ __launch_bounds__(256, 1)
void scan_kernel()
{
    const int bh = blockIdx.x >> 1;
    const int half = blockIdx.x & 1;
    const int b = bh >> 4;
    const int h = bh & 15;
    __shared__ __align__(16) float s[4][256];
    __shared__ float sbv[4];

    const int t = threadIdx.x;
    const int d = half * 32 + (t >> 3);
    const int cg = t & 7;
    const int cbase = cg * 8;

    const int arr = t >> 6;
    const int idx = t & 63;
    const float* src = g_QKVG + (size_t)arr * CC + (size_t)h * DD + idx;
    const size_t rbase = (size_t)b * TT;

    float Mreg[8];
#pragma unroll
    for (int j = 0; j < 8; j++) Mreg[j] = 0.0f;

    float f0a = src[(rbase + 0) * NFUSE], f0b = src[(rbase + 1) * NFUSE];
    float f1a = src[(rbase + 2) * NFUSE], f1b = src[(rbase + 3) * NFUSE];
    float f2a = src[(rbase + 4) * NFUSE], f2b = src[(rbase + 5) * NFUSE];
    float f3a = src[(rbase + 6) * NFUSE], f3b = src[(rbase + 7) * NFUSE];
    float b0a = 0, b0b = 0, b1a = 0, b1b = 0, b2a = 0, b2b = 0, b3a = 0, b3b = 0;
    if (t == 0) {
        b0a = g_Beta[(rbase + 0) * HH + h]; b0b = g_Beta[(rbase + 1) * HH + h];
        b1a = g_Beta[(rbase + 2) * HH + h]; b1b = g_Beta[(rbase + 3) * HH + h];
        b2a = g_Beta[(rbase + 4) * HH + h]; b2b = g_Beta[(rbase + 5) * HH + h];
        b3a = g_Beta[(rbase + 6) * HH + h]; b3b = g_Beta[(rbase + 7) * HH + h];
    }
    s[0][t] = f0a; s[1][t] = f0b;
    if (t == 0) { sbv[0] = b0a; sbv[1] = b0b; }
    __syncthreads();

#define SCAN_STEP2(STEP, RB0, RB1)                                                    \
    {                                                                                 \
        const float4* q1p = (const float4*)&s[RB0][cbase];                            \
        const float4* k1p = (const float4*)&s[RB0][64 + cbase];                       \
        const float4* q2p = (const float4*)&s[RB1][cbase];                            \
        const float4* k2p = (const float4*)&s[RB1][64 + cbase];                       \
        const float b1s = sbv[RB0], b2s = sbv[RB1];                                   \
        float4 q1a = q1p[0], q1b = q1p[1];                                            \
        float4 k1a = k1p[0], k1b = k1p[1];                                            \
        float4 q2a = q2p[0], q2b = q2p[1];                                            \
        float4 k2a = k2p[0], k2b = k2p[1];                                            \
        float po1 = 0, pk1 = 0, po2 = 0, pk2 = 0, ck = 0, cq = 0;                     \
        po1 = fmaf(Mreg[0], q1a.x, po1); po1 = fmaf(Mreg[1], q1a.y, po1);             \
        po1 = fmaf(Mreg[2], q1a.z, po1); po1 = fmaf(Mreg[3], q1a.w, po1);             \
        po1 = fmaf(Mreg[4], q1b.x, po1); po1 = fmaf(Mreg[5], q1b.y, po1);             \
        po1 = fmaf(Mreg[6], q1b.z, po1); po1 = fmaf(Mreg[7], q1b.w, po1);             \
        pk1 = fmaf(Mreg[0], k1a.x, pk1); pk1 = fmaf(Mreg[1], k1a.y, pk1);             \
        pk1 = fmaf(Mreg[2], k1a.z, pk1); pk1 = fmaf(Mreg[3], k1a.w, pk1);             \
        pk1 = fmaf(Mreg[4], k1b.x, pk1); pk1 = fmaf(Mreg[5], k1b.y, pk1);             \
        pk1 = fmaf(Mreg[6], k1b.z, pk1); pk1 = fmaf(Mreg[7], k1b.w, pk1);             \
        po2 = fmaf(Mreg[0], q2a.x, po2); po2 = fmaf(Mreg[1], q2a.y, po2);             \
        po2 = fmaf(Mreg[2], q2a.z, po2); po2 = fmaf(Mreg[3], q2a.w, po2);             \
        po2 = fmaf(Mreg[4], q2b.x, po2); po2 = fmaf(Mreg[5], q2b.y, po2);             \
        po2 = fmaf(Mreg[6], q2b.z, po2); po2 = fmaf(Mreg[7], q2b.w, po2);             \
        pk2 = fmaf(Mreg[0], k2a.x, pk2); pk2 = fmaf(Mreg[1], k2a.y, pk2);             \
        pk2 = fmaf(Mreg[2], k2a.z, pk2); pk2 = fmaf(Mreg[3], k2a.w, pk2);             \
        pk2 = fmaf(Mreg[4], k2b.x, pk2); pk2 = fmaf(Mreg[5], k2b.y, pk2);             \
        pk2 = fmaf(Mreg[6], k2b.z, pk2); pk2 = fmaf(Mreg[7], k2b.w, pk2);             \
        ck = fmaf(k1a.x, k2a.x, ck); ck = fmaf(k1a.y, k2a.y, ck);                     \
        ck = fmaf(k1a.z, k2a.z, ck); ck = fmaf(k1a.w, k2a.w, ck);                     \
        ck = fmaf(k1b.x, k2b.x, ck); ck = fmaf(k1b.y, k2b.y, ck);                     \
        ck = fmaf(k1b.z, k2b.z, ck); ck = fmaf(k1b.w, k2b.w, ck);                     \
        cq = fmaf(k1a.x, q2a.x, cq); cq = fmaf(k1a.y, q2a.y, cq);                     \
        cq = fmaf(k1a.z, q2a.z, cq); cq = fmaf(k1a.w, q2a.w, cq);                     \
        cq = fmaf(k1b.x, q2b.x, cq); cq = fmaf(k1b.y, q2b.y, cq);                     \
        cq = fmaf(k1b.z, q2b.z, cq); cq = fmaf(k1b.w, q2b.w, cq);                     \
        _Pragma("unroll")                                                             \
        for (int off = 1; off <= 4; off <<= 1) {                                      \
            po1 += __shfl_xor_sync(0xffffffffu, po1, off);                            \
            pk1 += __shfl_xor_sync(0xffffffffu, pk1, off);                            \
            po2 += __shfl_xor_sync(0xffffffffu, po2, off);                            \
            pk2 += __shfl_xor_sync(0xffffffffu, pk2, off);                            \
            ck  += __shfl_xor_sync(0xffffffffu, ck,  off);                            \
            cq  += __shfl_xor_sync(0xffffffffu, cq,  off);                            \
        }                                                                             \
        const float dv1 = s[RB0][128 + d] - pk1;                                      \
        const float bd1 = b1s * dv1;                                                  \
        const float pk2c = fmaf(bd1, ck, pk2);                                        \
        const float dv2 = s[RB1][128 + d] - pk2c;                                     \
        const float bd2 = b2s * dv2;                                                  \
        const float po2c = fmaf(bd1, cq, po2);                                        \
        Mreg[0] = fmaf(bd2, k2a.x, fmaf(bd1, k1a.x, Mreg[0]));                        \
        Mreg[1] = fmaf(bd2, k2a.y, fmaf(bd1, k1a.y, Mreg[1]));                        \
        Mreg[2] = fmaf(bd2, k2a.z, fmaf(bd1, k1a.z, Mreg[2]));                        \
        Mreg[3] = fmaf(bd2, k2a.w, fmaf(bd1, k1a.w, Mreg[3]));                        \
        Mreg[4] = fmaf(bd2, k2b.x, fmaf(bd1, k1b.x, Mreg[4]));                        \
        Mreg[5] = fmaf(bd2, k2b.y, fmaf(bd1, k1b.y, Mreg[5]));                        \
        Mreg[6] = fmaf(bd2, k2b.z, fmaf(bd1, k1b.z, Mreg[6]));                        \
        Mreg[7] = fmaf(bd2, k2b.w, fmaf(bd1, k1b.w, Mreg[7]));                        \
        if (cg == 0) {                                                                \
            g_OGh[(rbase + (STEP))     * CC + h * DD + d] =                           \
                __float2half(s[RB0][192 + d] * po1);                                  \
            g_OGh[(rbase + (STEP) + 1) * CC + h * DD + d] =                           \
                __float2half(s[RB1][192 + d] * po2c);                                 \
        }                                                                             \
    }

#define WINDOW(J, RB0, RB1, WB0, WB1, SFA, SFB, SBA, SBB, LFA, LFB, LBA, LBB)         \
    {                                                                                 \
        int ls = 2 * (J) + 8; if (ls > TT - 2) ls = TT - 2;                           \
        LFA = src[(rbase + ls) * NFUSE];                                              \
        LFB = src[(rbase + ls + 1) * NFUSE];                                          \
        if (t == 0) {                                                                 \
            LBA = g_Beta[(rbase + ls) * HH + h];                                      \
            LBB = g_Beta[(rbase + ls + 1) * HH + h];                                  \
        }                                                                             \
        s[WB0][t] = SFA; s[WB1][t] = SFB;                                             \
        if (t == 0) { sbv[WB0] = SBA; sbv[WB1] = SBB; }                               \
        SCAN_STEP2(2 * (J), RB0, RB1);                                                \
        __syncthreads();                                                              \
    }

    for (int m = 0; m < TT / 8; m++) {
        const int j0 = 4 * m;
        WINDOW(j0 + 0, 0, 1, 2, 3, f1a, f1b, b1a, b1b, f0a, f0b, b0a, b0b);
        WINDOW(j0 + 1, 2, 3, 0, 1, f2a, f2b, b2a, b2b, f1a, f1b, b1a, b1b);
        WINDOW(j0 + 2, 0, 1, 2, 3, f3a, f3b, b3a, b3b, f2a, f2b, b2a, b2b);
        WINDOW(j0 + 3, 2, 3, 0, 1, f0a, f0b, b0a, b0b, f3a, f3b, b3a, b3b);
    }
#undef WINDOW
#undef SCAN_STEP2
}

// ---------------------------------------------------------------------------
extern "C" void kernel_launch(void* const* d_in, const int* in_sizes, int n_in,
                              void* d_out, int out_size)
{
    const float* x     = (const float*)d_in[0];
    const float* Wq    = (const float*)d_in[1];
    const float* Wk    = (const float*)d_in[2];
    const float* Wv    = (const float*)d_in[3];
    const float* Wbeta = (const float*)d_in[4];
    const float* bbeta = (const float*)d_in[5];
    const float* Wgate = (const float*)d_in[6];
    const float* Wo    = (const float*)d_in[7];
    float* out = (float*)d_out;

    float *QKVGp, *Bp;
    __half *xhp, *whp, *oghp;
    cudaGetSymbolAddress((void**)&QKVGp, g_QKVG);
    cudaGetSymbolAddress((void**)&Bp,    g_Beta);
    cudaGetSymbolAddress((void**)&xhp,   g_xh);
    cudaGetSymbolAddress((void**)&whp,   g_wh);
    cudaGetSymbolAddress((void**)&oghp,  g_OGh);

    cudaFuncSetAttribute(hgemm, cudaFuncAttributeMaxDynamicSharedMemorySize, GEMM_SMEM);

    const int WSZ = CC * CC;

    // conversions: x unscaled fp16; weights 64x-scaled fp16
    h_conv_kernel<<<MROWS * CC / 4 / 256, 256>>>(x, xhp, 1.0f);
    whalf_kernel<<<5 * WSZ / 4 / 256, 256>>>(Wq, Wk, Wv, Wgate, Wo, whp);

    // fused QKVG projection: N=4096, sigmoid on gate quarter (cols >= 3072)
    dim3 fgrid(NFUSE / 128, MROWS / 128);
    hgemm<<<fgrid, 256, GEMM_SMEM>>>(xhp, whp, QKVGp, NFUSE, 3 * CC);

    beta_kernel<<<MROWS / 16, 512>>>(x, Wbeta, bbeta, Bp);
    norm_kernel<<<(2 * MROWS * HH) / 8, 256>>>();
    scan_kernel<<<2 * BB * HH, 256>>>();

    dim3 ogrid(CC / 128, MROWS / 128);
    hgemm<<<ogrid, 256, GEMM_SMEM>>>(oghp, whp + 4 * WSZ, out, CC, 1 << 30);
}

// round 17
// speedup vs baseline: 2.6322x; 1.0395x over previous
#include <cuda_runtime.h>
#include <cuda_fp16.h>
#include <math.h>
#include <stdint.h>

// Problem dims (fixed)
#define BB 4
#define TT 2048
#define CC 1024
#define HH 16
#define DD 64
#define MROWS (BB*TT)          // 8192
#define NFUSE 4096             // Q|K|V|G fused width
#define NPAD  4224             // + 128-wide beta tile column
#define WSCALE 64.0f
#define WINV   (1.0f/64.0f)

// ---------------------------------------------------------------------------
// Device scratch (cudaMalloc banned)
// Weight buffer layout (rows of 1024 fp16): [Wq|Wk|Wv|Wg| betaPad(128) | Wo]
// ---------------------------------------------------------------------------
__device__ float g_QKVG[MROWS*NFUSE];     // fused Q|K|V|G fp32
__device__ float g_Beta[MROWS*HH];
__device__ __half g_xh[MROWS*CC];         // fp16 x
__device__ __half g_wh[(5*CC + 128)*CC];  // fp16 64*W + beta pad
__device__ __half g_OGh[MROWS*CC];        // fp16 gate*o

// ---------------------------------------------------------------------------
// PTX helpers (base-ISA only: mma.sync / ldmatrix / cp.async)
// ---------------------------------------------------------------------------
__device__ __forceinline__ uint32_t smem_u32(const void* p) {
    uint32_t a;
    asm("{ .reg .u64 t; cvta.to.shared.u64 t, %1; cvt.u32.u64 %0, t; }" : "=r"(a) : "l"(p));
    return a;
}
__device__ __forceinline__ void cp16(uint32_t dst, const void* src) {
    asm volatile("cp.async.cg.shared.global [%0], [%1], 16;" :: "r"(dst), "l"(src));
}
#define CP_COMMIT() asm volatile("cp.async.commit_group;" ::: "memory")
#define CP_WAIT1()  asm volatile("cp.async.wait_group 1;" ::: "memory")
#define CP_WAIT0()  asm volatile("cp.async.wait_group 0;" ::: "memory")

__device__ __forceinline__ void ldm_x4(uint32_t* r, uint32_t addr) {
    asm volatile("ldmatrix.sync.aligned.m8n8.x4.shared.b16 {%0,%1,%2,%3}, [%4];"
        : "=r"(r[0]), "=r"(r[1]), "=r"(r[2]), "=r"(r[3]) : "r"(addr));
}
// fp16 mma, fp32 accumulate
__device__ __forceinline__ void mma_f16(float* d, const uint32_t* a, const uint32_t* b) {
    asm volatile("mma.sync.aligned.m16n8k16.row.col.f32.f16.f16.f32 "
        "{%0,%1,%2,%3}, {%4,%5,%6,%7}, {%8,%9}, {%0,%1,%2,%3};"
        : "+f"(d[0]), "+f"(d[1]), "+f"(d[2]), "+f"(d[3])
        : "r"(a[0]), "r"(a[1]), "r"(a[2]), "r"(a[3]), "r"(b[0]), "r"(b[1]));
}

// ---------------------------------------------------------------------------
// fp32 -> fp16 conversion, float4-vectorized (x)
// ---------------------------------------------------------------------------
__global__ __launch_bounds__(256)
void h_conv_kernel(const float* __restrict__ in, __half* __restrict__ out)
{
    const int i = blockIdx.x * 256 + threadIdx.x;
    float4 v = ((const float4*)in)[i];
    __half2 lo = __floats2half2_rn(v.x, v.y);
    __half2 hi = __floats2half2_rn(v.z, v.w);
    ((__half2*)out)[2 * i + 0] = lo;
    ((__half2*)out)[2 * i + 1] = hi;
}

// weights (64x-scaled) + beta pad tile + Wo, one launch.
// Layout: rows [0,4096)=Wq..Wg, [4096,4224)=betaPad, [4224,5248)=Wo
__global__ __launch_bounds__(256)
void whalf_kernel(const float* __restrict__ w0, const float* __restrict__ w1,
                  const float* __restrict__ w2, const float* __restrict__ w3,
                  const float* __restrict__ w4, const float* __restrict__ wbeta,
                  __half* __restrict__ out)
{
    const int i = blockIdx.x * 256 + threadIdx.x;       // float4 index
    const int per = (CC * CC) / 4;                      // 262144
    const int bper = (128 * CC) / 4;                    // 32768
    float4 v;
    if (i < 4 * per) {
        const int which = i / per;
        const int local = i - which * per;
        const float* src = (which == 0) ? w0 : (which == 1) ? w1 :
                           (which == 2) ? w2 : w3;
        v = ((const float4*)src)[local];
    } else if (i < 4 * per + bper) {
        const int local = i - 4 * per;
        const int e = local * 4;
        const int row = e >> 10;            // 0..127
        if (row < HH) {
            v = ((const float4*)wbeta)[local - ((row * CC) >> 2) + ((row * CC) >> 2)];
            v = ((const float4*)(wbeta + (size_t)row * CC))[(e & 1023) >> 2];
        } else {
            v = make_float4(0.f, 0.f, 0.f, 0.f);
        }
    } else {
        const int local = i - 4 * per - bper;
        v = ((const float4*)w4)[local];
    }
    __half2 lo = __floats2half2_rn(v.x * WSCALE, v.y * WSCALE);
    __half2 hi = __floats2half2_rn(v.z * WSCALE, v.w * WSCALE);
    ((__half2*)out)[2 * i + 0] = lo;
    ((__half2*)out)[2 * i + 1] = hi;
}

// ---------------------------------------------------------------------------
// FP16 HMMA GEMM: C[8192,N] = (1/64) * A[8192,1024] @ B[N,1024]^T
// (core identical to verified R16)  Epilogue:
//   col <  sig_start          : plain
//   sig_start <= col < beta0  : sigmoid
//   col >= beta0              : sigmoid(acc/64 + bbias[col-beta0]) -> BetaOut
// ---------------------------------------------------------------------------
#define STG_B 32768
#define NSTG  3
#define GEMM_SMEM (NSTG*STG_B)   // 96 KB

__global__ __launch_bounds__(256, 2)
void hgemm(const __half* __restrict__ Ag, const __half* __restrict__ Bg,
           float* __restrict__ Cc, int ldc, int sig_start, int beta0,
           const float* __restrict__ bbias, float* __restrict__ BetaOut)
{
    extern __shared__ char smem[];
    const uint32_t sbase = smem_u32(smem);
    const int tid = threadIdx.x;
    const int lane = tid & 31;
    const int wid = tid >> 5;
    const int m_blk = blockIdx.y * 128;
    const int n_blk = blockIdx.x * 128;
    const int warp_m = (wid >> 2) * 64;
    const int warp_n = (wid & 3) * 32;

    const char* pA = (const char*)(Ag + (size_t)m_blk * CC);
    const char* pB = (const char*)(Bg + (size_t)n_blk * CC);

#define LOAD_STAGE(KT, STG) do {                                               \
    const uint32_t sb_ = sbase + (STG) * STG_B;                                \
    const int k0b_ = (KT) * 128;                                               \
    _Pragma("unroll")                                                          \
    for (int j = 0; j < 4; j++) {                                              \
        const int c_ = j * 256 + tid;                                          \
        const int r_ = c_ >> 3, q_ = c_ & 7;                                   \
        const uint32_t so_ = (uint32_t)(r_ * 128 + ((q_ ^ (r_ & 7)) * 16));    \
        const size_t go_ = (size_t)r_ * 2048 + k0b_ + q_ * 16;                 \
        cp16(sb_ + 0     + so_, pA + go_);                                     \
        cp16(sb_ + 16384 + so_, pB + go_);                                     \
    }                                                                          \
    CP_COMMIT();                                                               \
} while (0)

    float acc[4][4][4];
#pragma unroll
    for (int a = 0; a < 4; a++)
#pragma unroll
        for (int b = 0; b < 4; b++)
#pragma unroll
            for (int c = 0; c < 4; c++) acc[a][b][c] = 0.0f;

    const int ra = (lane & 7) + (lane & 8);
    const int ka = (lane >> 4) << 3;
    const int rb = (lane & 7) + ((lane & 16) >> 1);
    const int kb = lane & 8;
    const int sw = lane & 7;

    LOAD_STAGE(0, 0);
    LOAD_STAGE(1, 1);

    for (int kt = 0; kt < 16; kt++) {
        if (kt + 1 < 16) CP_WAIT1(); else CP_WAIT0();
        __syncthreads();
        const uint32_t st = sbase + (kt % NSTG) * STG_B;

#pragma unroll
        for (int k16 = 0; k16 < 64; k16 += 16) {
            uint32_t bh[2][4];
#pragma unroll
            for (int bi = 0; bi < 2; bi++) {
                const int n0 = warp_n + bi * 16;
                const uint32_t addr = st + 16384 + ((uint32_t)(n0 + rb) << 7)
                                    + ((uint32_t)(((k16 + kb) >> 3) ^ sw) << 4);
                ldm_x4(bh[bi], addr);
            }
#pragma unroll
            for (int mi = 0; mi < 4; mi++) {
                const int m0 = warp_m + mi * 16;
                const uint32_t addr = st + ((uint32_t)(m0 + ra) << 7)
                                    + ((uint32_t)(((k16 + ka) >> 3) ^ sw) << 4);
                uint32_t ah[4];
                ldm_x4(ah, addr);
#pragma unroll
                for (int ni = 0; ni < 4; ni++) {
                    uint32_t* bp = &bh[ni >> 1][(ni & 1) * 2];
                    mma_f16(acc[mi][ni], ah, bp);
                }
            }
        }
        __syncthreads();
        if (kt + 2 < 16) LOAD_STAGE(kt + 2, (kt + 2) % NSTG);
    }
#undef LOAD_STAGE

    // epilogue
    const int er = lane >> 2;
    const int ec = (lane & 3) * 2;
#pragma unroll
    for (int mi = 0; mi < 4; mi++) {
        const int row = m_blk + warp_m + mi * 16 + er;
#pragma unroll
        for (int ni = 0; ni < 4; ni++) {
            const int col = n_blk + warp_n + ni * 8 + ec;
            float v0 = acc[mi][ni][0] * WINV, v1 = acc[mi][ni][1] * WINV;
            float v2 = acc[mi][ni][2] * WINV, v3 = acc[mi][ni][3] * WINV;
            if (col < beta0) {
                if (col >= sig_start) {
                    v0 = 1.0f / (1.0f + expf(-v0));
                    v1 = 1.0f / (1.0f + expf(-v1));
                    v2 = 1.0f / (1.0f + expf(-v2));
                    v3 = 1.0f / (1.0f + expf(-v3));
                }
                float2 lo2 = {v0, v1}, hi2 = {v2, v3};
                *(float2*)&Cc[(size_t)row * ldc + col] = lo2;
                *(float2*)&Cc[(size_t)(row + 8) * ldc + col] = hi2;
            } else {
                const int bc = col - beta0;
                if (bc < HH) {
                    float b0 = 1.0f / (1.0f + expf(-(v0 + bbias[bc])));
                    float b1 = 1.0f / (1.0f + expf(-(v1 + bbias[bc + 1])));
                    float b2 = 1.0f / (1.0f + expf(-(v2 + bbias[bc])));
                    float b3 = 1.0f / (1.0f + expf(-(v3 + bbias[bc + 1])));
                    BetaOut[(size_t)row * HH + bc]           = b0;
                    BetaOut[(size_t)row * HH + bc + 1]       = b1;
                    BetaOut[(size_t)(row + 8) * HH + bc]     = b2;
                    BetaOut[(size_t)(row + 8) * HH + bc + 1] = b3;
                }
            }
        }
    }
}

// ---------------------------------------------------------------------------
// L2-normalize Q and K per (row, head) over D=64 (in fused QKVG buffer)
// ---------------------------------------------------------------------------
__global__ __launch_bounds__(256)
void norm_kernel()
{
    const int gw = blockIdx.x * 8 + (threadIdx.x >> 5);
    const int lane = threadIdx.x & 31;
    const int which = gw & 1;
    const int rem = gw >> 1;
    const int row = rem >> 4;
    const int h = rem & 15;
    float* p = &g_QKVG[(size_t)row * NFUSE + which * CC + h * DD];
    float v0 = p[lane];
    float v1 = p[lane + 32];
    float s = v0 * v0 + v1 * v1;
#pragma unroll
    for (int off = 16; off > 0; off >>= 1)
        s += __shfl_xor_sync(0xffffffffu, s, off);
    float n = sqrtf(s);
    float scale = 1.0f / fmaxf(n, 1e-12f);
    p[lane]      = v0 * scale;
    p[lane + 32] = v1 * scale;
}

// ---------------------------------------------------------------------------
// Delta-rule scan, ROW-SPLIT + WY-2 (verified R14/R16). Writes fp16 OG.
// ---------------------------------------------------------------------------
__global__ __launch_bounds__(256, 1)
void scan_kernel()
{
    const int bh = blockIdx.x >> 1;
    const int half = blockIdx.x & 1;
    const int b = bh >> 4;
    const int h = bh & 15;
    __shared__ __align__(16) float s[4][256];
    __shared__ float sbv[4];

    const int t = threadIdx.x;
    const int d = half * 32 + (t >> 3);
    const int cg = t & 7;
    const int cbase = cg * 8;

    const int arr = t >> 6;
    const int idx = t & 63;
    const float* src = g_QKVG + (size_t)arr * CC + (size_t)h * DD + idx;
    const size_t rbase = (size_t)b * TT;

    float Mreg[8];
#pragma unroll
    for (int j = 0; j < 8; j++) Mreg[j] = 0.0f;

    float f0a = src[(rbase + 0) * NFUSE], f0b = src[(rbase + 1) * NFUSE];
    float f1a = src[(rbase + 2) * NFUSE], f1b = src[(rbase + 3) * NFUSE];
    float f2a = src[(rbase + 4) * NFUSE], f2b = src[(rbase + 5) * NFUSE];
    float f3a = src[(rbase + 6) * NFUSE], f3b = src[(rbase + 7) * NFUSE];
    float b0a = 0, b0b = 0, b1a = 0, b1b = 0, b2a = 0, b2b = 0, b3a = 0, b3b = 0;
    if (t == 0) {
        b0a = g_Beta[(rbase + 0) * HH + h]; b0b = g_Beta[(rbase + 1) * HH + h];
        b1a = g_Beta[(rbase + 2) * HH + h]; b1b = g_Beta[(rbase + 3) * HH + h];
        b2a = g_Beta[(rbase + 4) * HH + h]; b2b = g_Beta[(rbase + 5) * HH + h];
        b3a = g_Beta[(rbase + 6) * HH + h]; b3b = g_Beta[(rbase + 7) * HH + h];
    }
    s[0][t] = f0a; s[1][t] = f0b;
    if (t == 0) { sbv[0] = b0a; sbv[1] = b0b; }
    __syncthreads();

#define SCAN_STEP2(STEP, RB0, RB1)                                                    \
    {                                                                                 \
        const float4* q1p = (const float4*)&s[RB0][cbase];                            \
        const float4* k1p = (const float4*)&s[RB0][64 + cbase];                       \
        const float4* q2p = (const float4*)&s[RB1][cbase];                            \
        const float4* k2p = (const float4*)&s[RB1][64 + cbase];                       \
        const float b1s = sbv[RB0], b2s = sbv[RB1];                                   \
        float4 q1a = q1p[0], q1b = q1p[1];                                            \
        float4 k1a = k1p[0], k1b = k1p[1];                                            \
        float4 q2a = q2p[0], q2b = q2p[1];                                            \
        float4 k2a = k2p[0], k2b = k2p[1];                                            \
        float po1 = 0, pk1 = 0, po2 = 0, pk2 = 0, ck = 0, cq = 0;                     \
        po1 = fmaf(Mreg[0], q1a.x, po1); po1 = fmaf(Mreg[1], q1a.y, po1);             \
        po1 = fmaf(Mreg[2], q1a.z, po1); po1 = fmaf(Mreg[3], q1a.w, po1);             \
        po1 = fmaf(Mreg[4], q1b.x, po1); po1 = fmaf(Mreg[5], q1b.y, po1);             \
        po1 = fmaf(Mreg[6], q1b.z, po1); po1 = fmaf(Mreg[7], q1b.w, po1);             \
        pk1 = fmaf(Mreg[0], k1a.x, pk1); pk1 = fmaf(Mreg[1], k1a.y, pk1);             \
        pk1 = fmaf(Mreg[2], k1a.z, pk1); pk1 = fmaf(Mreg[3], k1a.w, pk1);             \
        pk1 = fmaf(Mreg[4], k1b.x, pk1); pk1 = fmaf(Mreg[5], k1b.y, pk1);             \
        pk1 = fmaf(Mreg[6], k1b.z, pk1); pk1 = fmaf(Mreg[7], k1b.w, pk1);             \
        po2 = fmaf(Mreg[0], q2a.x, po2); po2 = fmaf(Mreg[1], q2a.y, po2);             \
        po2 = fmaf(Mreg[2], q2a.z, po2); po2 = fmaf(Mreg[3], q2a.w, po2);             \
        po2 = fmaf(Mreg[4], q2b.x, po2); po2 = fmaf(Mreg[5], q2b.y, po2);             \
        po2 = fmaf(Mreg[6], q2b.z, po2); po2 = fmaf(Mreg[7], q2b.w, po2);             \
        pk2 = fmaf(Mreg[0], k2a.x, pk2); pk2 = fmaf(Mreg[1], k2a.y, pk2);             \
        pk2 = fmaf(Mreg[2], k2a.z, pk2); pk2 = fmaf(Mreg[3], k2a.w, pk2);             \
        pk2 = fmaf(Mreg[4], k2b.x, pk2); pk2 = fmaf(Mreg[5], k2b.y, pk2);             \
        pk2 = fmaf(Mreg[6], k2b.z, pk2); pk2 = fmaf(Mreg[7], k2b.w, pk2);             \
        ck = fmaf(k1a.x, k2a.x, ck); ck = fmaf(k1a.y, k2a.y, ck);                     \
        ck = fmaf(k1a.z, k2a.z, ck); ck = fmaf(k1a.w, k2a.w, ck);                     \
        ck = fmaf(k1b.x, k2b.x, ck); ck = fmaf(k1b.y, k2b.y, ck);                     \
        ck = fmaf(k1b.z, k2b.z, ck); ck = fmaf(k1b.w, k2b.w, ck);                     \
        cq = fmaf(k1a.x, q2a.x, cq); cq = fmaf(k1a.y, q2a.y, cq);                     \
        cq = fmaf(k1a.z, q2a.z, cq); cq = fmaf(k1a.w, q2a.w, cq);                     \
        cq = fmaf(k1b.x, q2b.x, cq); cq = fmaf(k1b.y, q2b.y, cq);                     \
        cq = fmaf(k1b.z, q2b.z, cq); cq = fmaf(k1b.w, q2b.w, cq);                     \
        _Pragma("unroll")                                                             \
        for (int off = 1; off <= 4; off <<= 1) {                                      \
            po1 += __shfl_xor_sync(0xffffffffu, po1, off);                            \
            pk1 += __shfl_xor_sync(0xffffffffu, pk1, off);                            \
            po2 += __shfl_xor_sync(0xffffffffu, po2, off);                            \
            pk2 += __shfl_xor_sync(0xffffffffu, pk2, off);                            \
            ck  += __shfl_xor_sync(0xffffffffu, ck,  off);                            \
            cq  += __shfl_xor_sync(0xffffffffu, cq,  off);                            \
        }                                                                             \
        const float dv1 = s[RB0][128 + d] - pk1;                                      \
        const float bd1 = b1s * dv1;                                                  \
        const float pk2c = fmaf(bd1, ck, pk2);                                        \
        const float dv2 = s[RB1][128 + d] - pk2c;                                     \
        const float bd2 = b2s * dv2;                                                  \
        const float po2c = fmaf(bd1, cq, po2);                                        \
        Mreg[0] = fmaf(bd2, k2a.x, fmaf(bd1, k1a.x, Mreg[0]));                        \
        Mreg[1] = fmaf(bd2, k2a.y, fmaf(bd1, k1a.y, Mreg[1]));                        \
        Mreg[2] = fmaf(bd2, k2a.z, fmaf(bd1, k1a.z, Mreg[2]));                        \
        Mreg[3] = fmaf(bd2, k2a.w, fmaf(bd1, k1a.w, Mreg[3]));                        \
        Mreg[4] = fmaf(bd2, k2b.x, fmaf(bd1, k1b.x, Mreg[4]));                        \
        Mreg[5] = fmaf(bd2, k2b.y, fmaf(bd1, k1b.y, Mreg[5]));                        \
        Mreg[6] = fmaf(bd2, k2b.z, fmaf(bd1, k1b.z, Mreg[6]));                        \
        Mreg[7] = fmaf(bd2, k2b.w, fmaf(bd1, k1b.w, Mreg[7]));                        \
        if (cg == 0) {                                                                \
            g_OGh[(rbase + (STEP))     * CC + h * DD + d] =                           \
                __float2half(s[RB0][192 + d] * po1);                                  \
            g_OGh[(rbase + (STEP) + 1) * CC + h * DD + d] =                           \
                __float2half(s[RB1][192 + d] * po2c);                                 \
        }                                                                             \
    }

#define WINDOW(J, RB0, RB1, WB0, WB1, SFA, SFB, SBA, SBB, LFA, LFB, LBA, LBB)         \
    {                                                                                 \
        int ls = 2 * (J) + 8; if (ls > TT - 2) ls = TT - 2;                           \
        LFA = src[(rbase + ls) * NFUSE];                                              \
        LFB = src[(rbase + ls + 1) * NFUSE];                                          \
        if (t == 0) {                                                                 \
            LBA = g_Beta[(rbase + ls) * HH + h];                                      \
            LBB = g_Beta[(rbase + ls + 1) * HH + h];                                  \
        }                                                                             \
        s[WB0][t] = SFA; s[WB1][t] = SFB;                                             \
        if (t == 0) { sbv[WB0] = SBA; sbv[WB1] = SBB; }                               \
        SCAN_STEP2(2 * (J), RB0, RB1);                                                \
        __syncthreads();                                                              \
    }

    for (int m = 0; m < TT / 8; m++) {
        const int j0 = 4 * m;
        WINDOW(j0 + 0, 0, 1, 2, 3, f1a, f1b, b1a, b1b, f0a, f0b, b0a, b0b);
        WINDOW(j0 + 1, 2, 3, 0, 1, f2a, f2b, b2a, b2b, f1a, f1b, b1a, b1b);
        WINDOW(j0 + 2, 0, 1, 2, 3, f3a, f3b, b3a, b3b, f2a, f2b, b2a, b2b);
        WINDOW(j0 + 3, 2, 3, 0, 1, f0a, f0b, b0a, b0b, f3a, f3b, b3a, b3b);
    }
#undef WINDOW
#undef SCAN_STEP2
}

// ---------------------------------------------------------------------------
extern "C" void kernel_launch(void* const* d_in, const int* in_sizes, int n_in,
                              void* d_out, int out_size)
{
    const float* x     = (const float*)d_in[0];
    const float* Wq    = (const float*)d_in[1];
    const float* Wk    = (const float*)d_in[2];
    const float* Wv    = (const float*)d_in[3];
    const float* Wbeta = (const float*)d_in[4];
    const float* bbeta = (const float*)d_in[5];
    const float* Wgate = (const float*)d_in[6];
    const float* Wo    = (const float*)d_in[7];
    float* out = (float*)d_out;

    float *QKVGp, *Bp;
    __half *xhp, *whp, *oghp;
    cudaGetSymbolAddress((void**)&QKVGp, g_QKVG);
    cudaGetSymbolAddress((void**)&Bp,    g_Beta);
    cudaGetSymbolAddress((void**)&xhp,   g_xh);
    cudaGetSymbolAddress((void**)&whp,   g_wh);
    cudaGetSymbolAddress((void**)&oghp,  g_OGh);

    cudaFuncSetAttribute(hgemm, cudaFuncAttributeMaxDynamicSharedMemorySize, GEMM_SMEM);

    const int WSZ = CC * CC;

    // conversions
    h_conv_kernel<<<MROWS * CC / 4 / 256, 256>>>(x, xhp);
    whalf_kernel<<<(5 * WSZ + 128 * CC) / 4 / 256, 256>>>(Wq, Wk, Wv, Wgate, Wo, Wbeta, whp);

    // fused QKVG+beta projection: N=4224, sigmoid gate cols [3072,4096),
    // beta tile cols >= 4096 (bias + sigmoid -> g_Beta)
    dim3 fgrid(NPAD / 128, MROWS / 128);
    hgemm<<<fgrid, 256, GEMM_SMEM>>>(xhp, whp, QKVGp, NFUSE, 3 * CC, NFUSE, bbeta, Bp);

    norm_kernel<<<(2 * MROWS * HH) / 8, 256>>>();
    scan_kernel<<<2 * BB * HH, 256>>>();

    dim3 ogrid(CC / 128, MROWS / 128);
    hgemm<<<ogrid, 256, GEMM_SMEM>>>(oghp, whp + (size_t)(4 * CC + 128) * CC, out,
                                     CC, 1 << 30, 1 << 30, bbeta, Bp);
}